// round 1
// baseline (speedup 1.0000x reference)
#include <cuda_runtime.h>
#include <cuda_bf16.h>
#include <cstdint>

#define BB   128
#define TT   256
#define CC   384
#define HH   6
#define DD   64
#define HID  1536
#define MM   (BB*TT)   // 32768

// ---------------- scratch (alloc-free: __device__ globals) ----------------
__device__ float g_h[(size_t)MM*CC];        // ln1 out, reused for ln2 out
__device__ float g_q[(size_t)BB*HH*TT*DD];
__device__ float g_k[(size_t)BB*HH*TT*DD];
__device__ float g_v[(size_t)BB*HH*TT*DD];
__device__ float g_attn[(size_t)MM*CC];     // concatenated attention output
__device__ float g_hidden[(size_t)MM*HID];

// ---------------- layernorm ----------------
__global__ void ln_kernel(const float* __restrict__ x, const float* __restrict__ g,
                          const float* __restrict__ b, float* __restrict__ out)
{
    int row = blockIdx.x;
    const float* xr = x + (size_t)row*CC;
    int t = threadIdx.x;           // 128 threads, 3 elems each
    float v0 = xr[t], v1 = xr[t+128], v2 = xr[t+256];
    float s  = v0+v1+v2;
    float ss = v0*v0 + v1*v1 + v2*v2;
    #pragma unroll
    for (int o = 16; o > 0; o >>= 1) {
        s  += __shfl_xor_sync(0xffffffffu, s,  o);
        ss += __shfl_xor_sync(0xffffffffu, ss, o);
    }
    __shared__ float sh_s[4], sh_ss[4];
    int w = t >> 5, lane = t & 31;
    if (lane == 0) { sh_s[w] = s; sh_ss[w] = ss; }
    __syncthreads();
    s  = sh_s[0]  + sh_s[1]  + sh_s[2]  + sh_s[3];
    ss = sh_ss[0] + sh_ss[1] + sh_ss[2] + sh_ss[3];
    float mean = s * (1.f/CC);
    float var  = ss * (1.f/CC) - mean*mean;
    float rstd = rsqrtf(var + 1e-5f);
    float* orow = out + (size_t)row*CC;
    orow[t]     = (v0-mean)*rstd*g[t]     + b[t];
    orow[t+128] = (v1-mean)*rstd*g[t+128] + b[t+128];
    orow[t+256] = (v2-mean)*rstd*g[t+256] + b[t+256];
}

// ---------------- generic tiled SGEMM with fused epilogues ----------------
// C_out[m,n] = sum_k A[m,k]*B[k,n]  (+bias)(relu)(+res)(accumulate)
// HEAD_B: B stored [H, C, D] (per-head weight), column n = h*64+d
// QKV_OUT: output stored [B, H, T, D] with m=b*T+t, n=h*64+d
#define GBM 128
#define GBN 128
#define GBK 8

template<bool HEAD_B, bool QKV_OUT, bool HAS_BIAS, bool DO_RELU, bool HAS_RES, bool ACC>
__global__ __launch_bounds__(256)
void gemm_kernel(const float* __restrict__ A, const float* __restrict__ Bw,
                 const float* __restrict__ bias, const float* __restrict__ res,
                 float* __restrict__ out, int K, int N)
{
    __shared__ float As[GBK][GBM];
    __shared__ float Bs[GBK][GBN];

    int tid = threadIdx.x;
    int bm = blockIdx.y * GBM;
    int bn = blockIdx.x * GBN;
    int ty = tid >> 4;          // 0..15
    int tx = tid & 15;          // 0..15

    float acc[8][8];
    #pragma unroll
    for (int i = 0; i < 8; i++)
        #pragma unroll
        for (int j = 0; j < 8; j++) acc[i][j] = 0.f;

    int arow  = tid >> 1;            // 0..127
    int akq   = (tid & 1) * 4;       // 0 or 4
    int bkrow = tid >> 5;            // 0..7
    int bcol  = (tid & 31) * 4;      // 0..124

    const float* Aptr = A + (size_t)(bm + arow) * K + akq;

    // precompute head-mode B base (column group fixed per thread)
    const float* Bbase;
    if (HEAD_B) {
        int n  = bn + bcol;
        int hh = n >> 6, dd = n & 63;
        Bbase = Bw + ((size_t)hh * CC) * DD + dd + (size_t)bkrow * DD;
    } else {
        Bbase = Bw + (size_t)bkrow * N + bn + bcol;
    }

    for (int k0 = 0; k0 < K; k0 += GBK) {
        float4 af = *(const float4*)(Aptr + k0);
        As[akq+0][arow] = af.x;
        As[akq+1][arow] = af.y;
        As[akq+2][arow] = af.z;
        As[akq+3][arow] = af.w;

        float4 bf;
        if (HEAD_B) bf = *(const float4*)(Bbase + (size_t)k0 * DD);
        else        bf = *(const float4*)(Bbase + (size_t)k0 * N);
        *(float4*)&Bs[bkrow][bcol] = bf;

        __syncthreads();
        #pragma unroll
        for (int k = 0; k < GBK; k++) {
            float a[8], bb[8];
            *(float4*)&a[0]  = *(const float4*)&As[k][ty*8];
            *(float4*)&a[4]  = *(const float4*)&As[k][ty*8+4];
            *(float4*)&bb[0] = *(const float4*)&Bs[k][tx*8];
            *(float4*)&bb[4] = *(const float4*)&Bs[k][tx*8+4];
            #pragma unroll
            for (int i = 0; i < 8; i++)
                #pragma unroll
                for (int j = 0; j < 8; j++)
                    acc[i][j] += a[i] * bb[j];
        }
        __syncthreads();
    }

    #pragma unroll
    for (int i = 0; i < 8; i++) {
        int m = bm + ty*8 + i;
        #pragma unroll
        for (int j = 0; j < 8; j++) {
            int n = bn + tx*8 + j;
            float v = acc[i][j];
            if (HAS_BIAS) v += bias[n];
            if (DO_RELU)  v  = fmaxf(v, 0.f);
            if (HAS_RES)  v += res[(size_t)m * N + n];
            if (QKV_OUT) {
                int bidx = m / TT, t = m % TT, hh = n >> 6, dd = n & 63;
                out[(((size_t)bidx*HH + hh)*TT + t)*DD + dd] = v;
            } else {
                size_t idx = (size_t)m * N + n;
                if (ACC) out[idx] += v; else out[idx] = v;
            }
        }
    }
}

// ---------------- causal attention (online softmax, one row/thread) ----------------
// grid: B*H blocks, 256 threads; K/V tiles staged in 128KB dynamic smem.
__global__ __launch_bounds__(256)
void attn_kernel(const float* __restrict__ q, const float* __restrict__ k,
                 const float* __restrict__ v, float* __restrict__ out)
{
    extern __shared__ float smem[];
    float* Ks = smem;            // [T][D]
    float* Vs = smem + TT*DD;    // [T][D]

    int bh = blockIdx.x;
    int b  = bh / HH;
    int h  = bh % HH;
    int tid = threadIdx.x;       // query row index, 0..255

    const float* kb = k + (size_t)bh * TT * DD;
    const float* vb = v + (size_t)bh * TT * DD;

    for (int i = tid*4; i < TT*DD; i += 256*4) {
        *(float4*)&Ks[i] = *(const float4*)&kb[i];
        *(float4*)&Vs[i] = *(const float4*)&vb[i];
    }

    float qr[64];
    const float* qp = q + (size_t)bh * TT * DD + (size_t)tid * DD;
    #pragma unroll
    for (int i = 0; i < 16; i++)
        *(float4*)&qr[i*4] = *(const float4*)&qp[i*4];

    __syncthreads();

    float o[64];
    #pragma unroll
    for (int d = 0; d < 64; d++) o[d] = 0.f;
    float mx = -1e30f, l = 0.f;
    const float scale = rsqrtf((float)CC);   // reference scales by C^-0.5

    for (int j = 0; j <= tid; j++) {
        float s = 0.f;
        const float* kr = &Ks[j*64];
        #pragma unroll
        for (int d = 0; d < 64; d++) s += qr[d] * kr[d];
        s *= scale;
        float mn = fmaxf(mx, s);
        float c  = __expf(mx - mn);
        float p  = __expf(s  - mn);
        l = l * c + p;
        const float* vr = &Vs[j*64];
        #pragma unroll
        for (int d = 0; d < 64; d++) o[d] = o[d]*c + p*vr[d];
        mx = mn;
    }

    float inv = 1.f / l;
    float* op = out + ((size_t)b*TT + tid)*CC + h*DD;
    #pragma unroll
    for (int d = 0; d < 64; d++) op[d] = o[d]*inv;
}

// ---------------- launch ----------------
extern "C" void kernel_launch(void* const* d_in, const int* in_sizes, int n_in,
                              void* d_out, int out_size)
{
    const float* x      = (const float*)d_in[0];
    const float* wq     = (const float*)d_in[1];
    const float* wk     = (const float*)d_in[2];
    const float* wv     = (const float*)d_in[3];
    const float* w_proj = (const float*)d_in[4];
    const float* b_proj = (const float*)d_in[5];
    const float* w1     = (const float*)d_in[6];
    const float* b1     = (const float*)d_in[7];
    const float* w2     = (const float*)d_in[8];
    const float* b2     = (const float*)d_in[9];
    const float* ln1_g  = (const float*)d_in[10];
    const float* ln1_b  = (const float*)d_in[11];
    const float* ln2_g  = (const float*)d_in[12];
    const float* ln2_b  = (const float*)d_in[13];
    float* out = (float*)d_out;

    void* p;
    cudaGetSymbolAddress(&p, g_h);      float* h    = (float*)p;
    cudaGetSymbolAddress(&p, g_q);      float* q    = (float*)p;
    cudaGetSymbolAddress(&p, g_k);      float* k    = (float*)p;
    cudaGetSymbolAddress(&p, g_v);      float* v    = (float*)p;
    cudaGetSymbolAddress(&p, g_attn);   float* attn = (float*)p;
    cudaGetSymbolAddress(&p, g_hidden); float* hid  = (float*)p;

    const int ATTN_SMEM = 2 * TT * DD * sizeof(float);  // 131072
    cudaFuncSetAttribute(attn_kernel, cudaFuncAttributeMaxDynamicSharedMemorySize, ATTN_SMEM);

    // 1. LN1
    ln_kernel<<<MM, 128>>>(x, ln1_g, ln1_b, h);

    // 2. QKV projections (per-head weights), output [B,H,T,D]
    dim3 gqkv(CC/GBN, MM/GBM);
    gemm_kernel<true,  true,  false, false, false, false><<<gqkv, 256>>>(h, wq, nullptr, nullptr, q, CC, CC);
    gemm_kernel<true,  true,  false, false, false, false><<<gqkv, 256>>>(h, wk, nullptr, nullptr, k, CC, CC);
    gemm_kernel<true,  true,  false, false, false, false><<<gqkv, 256>>>(h, wv, nullptr, nullptr, v, CC, CC);

    // 3. causal attention -> concat [M, C]
    attn_kernel<<<BB*HH, 256, ATTN_SMEM>>>(q, k, v, attn);

    // 4. proj + bias + residual(x) -> d_out  (d_out holds residual-1 "y")
    gemm_kernel<false, false, true,  false, true,  false><<<dim3(CC/GBN, MM/GBM), 256>>>(attn, w_proj, b_proj, x, out, CC, CC);

    // 5. LN2 (reads d_out)
    ln_kernel<<<MM, 128>>>(out, ln2_g, ln2_b, h);

    // 6. MLP fc1 + bias + relu -> hidden
    gemm_kernel<false, false, true,  true,  false, false><<<dim3(HID/GBN, MM/GBM), 256>>>(h, w1, b1, nullptr, hid, CC, HID);

    // 7. MLP fc2 + bias, accumulate into d_out (y + mlp)
    gemm_kernel<false, false, true,  false, false, true ><<<dim3(CC/GBN, MM/GBM), 256>>>(hid, w2, b2, nullptr, out, HID, CC);
}

// round 3
// speedup vs baseline: 2.1378x; 2.1378x over previous
#include <cuda_runtime.h>
#include <cuda_bf16.h>
#include <cstdint>

#define BB   128
#define TT   256
#define CC   384
#define HH   6
#define DD   64
#define HID  1536
#define MM   (BB*TT)   // 32768

// GEMM tiling
#define BM 128
#define BN 128
#define BK 32
#define ASTR 36            // A smem row stride (floats), conflict-free for frag loads
#define BSTR 136           // B smem row stride (floats)
#define A_BUF (BM*ASTR)    // 4608 floats
#define B_BUF (BK*BSTR)    // 4352 floats
#define GEMM_SMEM_BYTES ((2*A_BUF + 2*B_BUF)*4)   // 71680

// ---------------- scratch (alloc-free: __device__ globals) ----------------
__device__ float g_h[(size_t)MM*CC];
__device__ float g_q[(size_t)BB*HH*TT*DD];
__device__ float g_k[(size_t)BB*HH*TT*DD];
__device__ float g_v[(size_t)BB*HH*TT*DD];
__device__ float g_attn[(size_t)MM*CC];
__device__ float g_hidden[(size_t)MM*HID];

// ---------------- helpers ----------------
__device__ __forceinline__ uint32_t f2tf32(float f) {
    uint32_t r;
    asm("cvt.rna.tf32.f32 %0, %1;" : "=r"(r) : "f"(f));
    return r;
}
__device__ __forceinline__ void cp_async16(uint32_t s, const float* g) {
    asm volatile("cp.async.cg.shared.global [%0], [%1], 16;\n" :: "r"(s), "l"(g));
}
__device__ __forceinline__ void cp_commit() {
    asm volatile("cp.async.commit_group;\n");
}
template<int N> __device__ __forceinline__ void cp_wait() {
    asm volatile("cp.async.wait_group %0;\n" :: "n"(N));
}

// ---------------- layernorm ----------------
__global__ void ln_kernel(const float* __restrict__ x, const float* __restrict__ g,
                          const float* __restrict__ b, float* __restrict__ out)
{
    int row = blockIdx.x;
    const float* xr = x + (size_t)row*CC;
    int t = threadIdx.x;           // 128 threads, 3 elems each
    float v0 = xr[t], v1 = xr[t+128], v2 = xr[t+256];
    float s  = v0+v1+v2;
    float ss = v0*v0 + v1*v1 + v2*v2;
    #pragma unroll
    for (int o = 16; o > 0; o >>= 1) {
        s  += __shfl_xor_sync(0xffffffffu, s,  o);
        ss += __shfl_xor_sync(0xffffffffu, ss, o);
    }
    __shared__ float sh_s[4], sh_ss[4];
    int w = t >> 5, lane = t & 31;
    if (lane == 0) { sh_s[w] = s; sh_ss[w] = ss; }
    __syncthreads();
    s  = sh_s[0]  + sh_s[1]  + sh_s[2]  + sh_s[3];
    ss = sh_ss[0] + sh_ss[1] + sh_ss[2] + sh_ss[3];
    float mean = s * (1.f/CC);
    float var  = ss * (1.f/CC) - mean*mean;
    float rstd = rsqrtf(var + 1e-5f);
    float* orow = out + (size_t)row*CC;
    orow[t]     = (v0-mean)*rstd*g[t]     + b[t];
    orow[t+128] = (v1-mean)*rstd*g[t+128] + b[t+128];
    orow[t+256] = (v2-mean)*rstd*g[t+256] + b[t+256];
}

// ---------------- tf32 tensor-core GEMM with fused epilogues ----------------
// out[m,n] = sum_k A[m,k]*B[k,n]  (+bias)(relu)(+res)(accumulate)
// HEAD_B: B stored [H, C, D], column n = h*64+d
// QKV_OUT: out stored [B, H, T, D], m = b*T+t, n = h*64+d
template<bool HEAD_B, bool QKV_OUT, bool HAS_BIAS, bool DO_RELU, bool HAS_RES, bool ACC>
__global__ __launch_bounds__(256)
void gemm_tc(const float* __restrict__ A, const float* __restrict__ Bw,
             const float* __restrict__ bias, const float* __restrict__ res,
             float* __restrict__ out, int K, int N)
{
    extern __shared__ float smem[];
    uint32_t smem_u32 = (uint32_t)__cvta_generic_to_shared(smem);

    const int tid  = threadIdx.x;
    const int bm   = blockIdx.y * BM;
    const int bn   = blockIdx.x * BN;
    const int warp = tid >> 5, lane = tid & 31;
    const int wm   = (warp >> 1) * 32;    // warp row base within CTA tile
    const int wn   = (warp & 1)  * 64;    // warp col base
    const int gid  = lane >> 2, tig = lane & 3;

    // global-load coords (4 x 16B per matrix per thread per k-tile)
    const int a_r0 = tid >> 3;            // +i*32
    const int a_c  = (tid & 7) * 4;
    const int b_k0 = tid >> 5;            // +i*8
    const int b_c  = (tid & 31) * 4;

    float acc[2][8][4];
    #pragma unroll
    for (int mt = 0; mt < 2; mt++)
        #pragma unroll
        for (int nt = 0; nt < 8; nt++)
            #pragma unroll
            for (int r = 0; r < 4; r++) acc[mt][nt][r] = 0.f;

    auto load_tile = [&](int k0, int buf) {
        #pragma unroll
        for (int i = 0; i < 4; i++) {
            int row = a_r0 + i*32;
            uint32_t s = smem_u32 + (uint32_t)(buf*A_BUF + row*ASTR + a_c)*4u;
            cp_async16(s, A + (size_t)(bm + row)*K + k0 + a_c);
        }
        #pragma unroll
        for (int i = 0; i < 4; i++) {
            int kr = b_k0 + i*8;
            uint32_t s = smem_u32 + (uint32_t)(2*A_BUF + buf*B_BUF + kr*BSTR + b_c)*4u;
            const float* g;
            if (HEAD_B) {
                int n = bn + b_c;
                g = Bw + ((size_t)(n >> 6)*CC + (k0 + kr))*DD + (n & 63);
            } else {
                g = Bw + (size_t)(k0 + kr)*N + bn + b_c;
            }
            cp_async16(s, g);
        }
        cp_commit();
    };

    const int ntiles = K / BK;
    load_tile(0, 0);

    for (int kt = 0; kt < ntiles; kt++) {
        int cur = kt & 1;
        if (kt + 1 < ntiles) { load_tile((kt+1)*BK, cur ^ 1); cp_wait<1>(); }
        else                 { cp_wait<0>(); }
        __syncthreads();

        const float* Ab = smem + cur*A_BUF;
        const float* Bb = smem + 2*A_BUF + cur*B_BUF;

        #pragma unroll
        for (int ks = 0; ks < 4; ks++) {
            const int k0 = ks * 8;
            uint32_t a[2][4];
            #pragma unroll
            for (int mt = 0; mt < 2; mt++) {
                const float* ap = Ab + (wm + mt*16 + gid)*ASTR + k0;
                // PTX m16n8k8.tf32 A layout:
                // a0=(gid, tig)  a1=(gid+8, tig)  a2=(gid, tig+4)  a3=(gid+8, tig+4)
                a[mt][0] = f2tf32(ap[tig]);
                a[mt][1] = f2tf32(ap[8*ASTR + tig]);
                a[mt][2] = f2tf32(ap[tig + 4]);
                a[mt][3] = f2tf32(ap[8*ASTR + tig + 4]);
            }
            uint32_t b[8][2];
            #pragma unroll
            for (int nt = 0; nt < 8; nt++) {
                const float* bp = Bb + (k0 + tig)*BSTR + wn + nt*8 + gid;
                b[nt][0] = f2tf32(bp[0]);
                b[nt][1] = f2tf32(bp[4*BSTR]);
            }
            #pragma unroll
            for (int mt = 0; mt < 2; mt++)
                #pragma unroll
                for (int nt = 0; nt < 8; nt++)
                    asm volatile(
                        "mma.sync.aligned.m16n8k8.row.col.f32.tf32.tf32.f32 "
                        "{%0,%1,%2,%3}, {%4,%5,%6,%7}, {%8,%9}, {%0,%1,%2,%3};"
                        : "+f"(acc[mt][nt][0]), "+f"(acc[mt][nt][1]),
                          "+f"(acc[mt][nt][2]), "+f"(acc[mt][nt][3])
                        : "r"(a[mt][0]), "r"(a[mt][1]), "r"(a[mt][2]), "r"(a[mt][3]),
                          "r"(b[nt][0]), "r"(b[nt][1]));
        }
        __syncthreads();
    }

    // epilogue: c0=(gid, 2tig) c1=(gid, 2tig+1) c2=(gid+8, 2tig) c3=(gid+8, 2tig+1)
    #pragma unroll
    for (int mt = 0; mt < 2; mt++) {
        #pragma unroll
        for (int nt = 0; nt < 8; nt++) {
            #pragma unroll
            for (int r = 0; r < 4; r++) {
                int row = bm + wm + mt*16 + gid + ((r >= 2) ? 8 : 0);
                int col = bn + wn + nt*8 + tig*2 + (r & 1);
                float v = acc[mt][nt][r];
                if (HAS_BIAS) v += bias[col];
                if (DO_RELU)  v  = fmaxf(v, 0.f);
                if (HAS_RES)  v += res[(size_t)row*N + col];
                if (QKV_OUT) {
                    int bidx = row / TT, t = row % TT, h = col >> 6, d = col & 63;
                    out[(((size_t)bidx*HH + h)*TT + t)*DD + d] = v;
                } else {
                    size_t idx = (size_t)row*N + col;
                    if (ACC) out[idx] += v; else out[idx] = v;
                }
            }
        }
    }
}

// ---------------- causal attention (online softmax, one row/thread) ----------------
__global__ __launch_bounds__(256)
void attn_kernel(const float* __restrict__ q, const float* __restrict__ k,
                 const float* __restrict__ v, float* __restrict__ out)
{
    extern __shared__ float smem[];
    float* Ks = smem;            // [T][D]
    float* Vs = smem + TT*DD;    // [T][D]

    int bh = blockIdx.x;
    int b  = bh / HH;
    int h  = bh % HH;
    int tid = threadIdx.x;       // query row, 0..255

    const float* kb = k + (size_t)bh * TT * DD;
    const float* vb = v + (size_t)bh * TT * DD;

    for (int i = tid*4; i < TT*DD; i += 256*4) {
        *(float4*)&Ks[i] = *(const float4*)&kb[i];
        *(float4*)&Vs[i] = *(const float4*)&vb[i];
    }

    float qr[64];
    const float* qp = q + (size_t)bh * TT * DD + (size_t)tid * DD;
    #pragma unroll
    for (int i = 0; i < 16; i++)
        *(float4*)&qr[i*4] = *(const float4*)&qp[i*4];

    __syncthreads();

    float o[64];
    #pragma unroll
    for (int d = 0; d < 64; d++) o[d] = 0.f;
    float mx = -1e30f, l = 0.f;
    const float scale = rsqrtf((float)CC);

    for (int j = 0; j <= tid; j++) {
        float s = 0.f;
        const float* kr = &Ks[j*64];
        #pragma unroll
        for (int d = 0; d < 64; d++) s += qr[d] * kr[d];
        s *= scale;
        float mn = fmaxf(mx, s);
        float c  = __expf(mx - mn);
        float p  = __expf(s  - mn);
        l = l * c + p;
        const float* vr = &Vs[j*64];
        #pragma unroll
        for (int d = 0; d < 64; d++) o[d] = o[d]*c + p*vr[d];
        mx = mn;
    }

    float inv = 1.f / l;
    float* op = out + ((size_t)b*TT + tid)*CC + h*DD;
    #pragma unroll
    for (int d = 0; d < 64; d++) op[d] = o[d]*inv;
}

// ---------------- launch ----------------
extern "C" void kernel_launch(void* const* d_in, const int* in_sizes, int n_in,
                              void* d_out, int out_size)
{
    const float* x      = (const float*)d_in[0];
    const float* wq     = (const float*)d_in[1];
    const float* wk     = (const float*)d_in[2];
    const float* wv     = (const float*)d_in[3];
    const float* w_proj = (const float*)d_in[4];
    const float* b_proj = (const float*)d_in[5];
    const float* w1     = (const float*)d_in[6];
    const float* b1     = (const float*)d_in[7];
    const float* w2     = (const float*)d_in[8];
    const float* b2     = (const float*)d_in[9];
    const float* ln1_g  = (const float*)d_in[10];
    const float* ln1_b  = (const float*)d_in[11];
    const float* ln2_g  = (const float*)d_in[12];
    const float* ln2_b  = (const float*)d_in[13];
    float* out = (float*)d_out;

    void* p;
    cudaGetSymbolAddress(&p, g_h);      float* h    = (float*)p;
    cudaGetSymbolAddress(&p, g_q);      float* q    = (float*)p;
    cudaGetSymbolAddress(&p, g_k);      float* k    = (float*)p;
    cudaGetSymbolAddress(&p, g_v);      float* v    = (float*)p;
    cudaGetSymbolAddress(&p, g_attn);   float* attn = (float*)p;
    cudaGetSymbolAddress(&p, g_hidden); float* hid  = (float*)p;

    const int ATTN_SMEM = 2 * TT * DD * sizeof(float);  // 131072
    cudaFuncSetAttribute(attn_kernel, cudaFuncAttributeMaxDynamicSharedMemorySize, ATTN_SMEM);

    // gemm template instantiations + smem attr
    auto* g_qkv  = gemm_tc<true,  true,  false, false, false, false>;
    auto* g_proj = gemm_tc<false, false, true,  false, true,  false>;
    auto* g_fc1  = gemm_tc<false, false, true,  true,  false, false>;
    auto* g_fc2  = gemm_tc<false, false, true,  false, false, true >;
    cudaFuncSetAttribute(g_qkv,  cudaFuncAttributeMaxDynamicSharedMemorySize, GEMM_SMEM_BYTES);
    cudaFuncSetAttribute(g_proj, cudaFuncAttributeMaxDynamicSharedMemorySize, GEMM_SMEM_BYTES);
    cudaFuncSetAttribute(g_fc1,  cudaFuncAttributeMaxDynamicSharedMemorySize, GEMM_SMEM_BYTES);
    cudaFuncSetAttribute(g_fc2,  cudaFuncAttributeMaxDynamicSharedMemorySize, GEMM_SMEM_BYTES);

    // 1. LN1
    ln_kernel<<<MM, 128>>>(x, ln1_g, ln1_b, h);

    // 2. QKV projections
    dim3 gqkv(CC/BN, MM/BM);
    g_qkv<<<gqkv, 256, GEMM_SMEM_BYTES>>>(h, wq, nullptr, nullptr, q, CC, CC);
    g_qkv<<<gqkv, 256, GEMM_SMEM_BYTES>>>(h, wk, nullptr, nullptr, k, CC, CC);
    g_qkv<<<gqkv, 256, GEMM_SMEM_BYTES>>>(h, wv, nullptr, nullptr, v, CC, CC);

    // 3. causal attention
    attn_kernel<<<BB*HH, 256, ATTN_SMEM>>>(q, k, v, attn);

    // 4. proj + bias + residual(x) -> d_out
    g_proj<<<dim3(CC/BN, MM/BM), 256, GEMM_SMEM_BYTES>>>(attn, w_proj, b_proj, x, out, CC, CC);

    // 5. LN2
    ln_kernel<<<MM, 128>>>(out, ln2_g, ln2_b, h);

    // 6. MLP fc1 + bias + relu
    g_fc1<<<dim3(HID/BN, MM/BM), 256, GEMM_SMEM_BYTES>>>(h, w1, b1, nullptr, hid, CC, HID);

    // 7. MLP fc2 + bias, accumulate into d_out
    g_fc2<<<dim3(CC/BN, MM/BM), 256, GEMM_SMEM_BYTES>>>(hid, w2, b2, nullptr, out, HID, CC);
}

// round 5
// speedup vs baseline: 2.4001x; 1.1227x over previous
#include <cuda_runtime.h>
#include <cuda_bf16.h>
#include <cstdint>

#define BB   128
#define TT   256
#define CC   384
#define HH   6
#define DD   64
#define HID  1536
#define MM   (BB*TT)   // 32768
#define NQKV 1152

// GEMM tiling
#define BM 128
#define BN 128
#define BK 32
#define ASTR 36
#define BSTR 136
#define A_BUF (BM*ASTR)
#define B_BUF (BK*BSTR)
#define GEMM_SMEM_BYTES ((2*A_BUF + 2*B_BUF)*4)   // 71680

// ---------------- scratch (alloc-free: __device__ globals) ----------------
__device__ float g_h[(size_t)MM*CC];
__device__ float g_q[(size_t)BB*HH*TT*DD];
__device__ float g_k[(size_t)BB*HH*TT*DD];
__device__ float g_v[(size_t)BB*HH*TT*DD];
__device__ float g_attn[(size_t)MM*CC];
__device__ float g_hidden[(size_t)MM*HID];
// tf32-pre-rounded weights, [k][n] layout
__device__ float g_w_qkv[(size_t)CC*NQKV];    // n = src*384 + h*64 + d
__device__ float g_w_proj[(size_t)CC*CC];
__device__ float g_w1[(size_t)CC*HID];
__device__ float g_w2[(size_t)HID*CC];

// ---------------- helpers ----------------
__device__ __forceinline__ uint32_t f2tf32(float f) {
    uint32_t r;
    asm("cvt.rna.tf32.f32 %0, %1;" : "=r"(r) : "f"(f));
    return r;
}
__device__ __forceinline__ float roundtf(float f) { return __uint_as_float(f2tf32(f)); }

__device__ __forceinline__ void cp_async16(uint32_t s, const float* g) {
    asm volatile("cp.async.cg.shared.global [%0], [%1], 16;\n" :: "r"(s), "l"(g));
}
__device__ __forceinline__ void cp_commit() {
    asm volatile("cp.async.commit_group;\n");
}
template<int N> __device__ __forceinline__ void cp_wait() {
    asm volatile("cp.async.wait_group %0;\n" :: "n"(N));
}

// ---------------- weight pack kernels (round to tf32, keep [k][n]) ----------------
__global__ void pack_rnd(const float* __restrict__ W, float* __restrict__ Wr, int count)
{
    int idx = blockIdx.x * blockDim.x + threadIdx.x;
    if (idx < count) Wr[idx] = roundtf(W[idx]);
}
__global__ void pack_qkv(const float* __restrict__ wq, const float* __restrict__ wk,
                         const float* __restrict__ wv, float* __restrict__ Wf)
{
    int idx = blockIdx.x * blockDim.x + threadIdx.x;   // idx = k*1152 + n
    if (idx >= CC*NQKV) return;
    int n = idx % NQKV, k = idx / NQKV;
    int src = n / CC, within = n % CC;
    int h = within >> 6, d = within & 63;
    const float* w = (src == 0) ? wq : (src == 1) ? wk : wv;
    Wf[idx] = roundtf(w[((size_t)h*CC + k)*DD + d]);
}

// ---------------- layernorm (tf32-rounded output) ----------------
__global__ void ln_kernel(const float* __restrict__ x, const float* __restrict__ g,
                          const float* __restrict__ b, float* __restrict__ out)
{
    int row = blockIdx.x;
    const float* xr = x + (size_t)row*CC;
    int t = threadIdx.x;
    float v0 = xr[t], v1 = xr[t+128], v2 = xr[t+256];
    float s  = v0+v1+v2;
    float ss = v0*v0 + v1*v1 + v2*v2;
    #pragma unroll
    for (int o = 16; o > 0; o >>= 1) {
        s  += __shfl_xor_sync(0xffffffffu, s,  o);
        ss += __shfl_xor_sync(0xffffffffu, ss, o);
    }
    __shared__ float sh_s[4], sh_ss[4];
    int w = t >> 5, lane = t & 31;
    if (lane == 0) { sh_s[w] = s; sh_ss[w] = ss; }
    __syncthreads();
    s  = sh_s[0]  + sh_s[1]  + sh_s[2]  + sh_s[3];
    ss = sh_ss[0] + sh_ss[1] + sh_ss[2] + sh_ss[3];
    float mean = s * (1.f/CC);
    float var  = ss * (1.f/CC) - mean*mean;
    float rstd = rsqrtf(var + 1e-5f);
    float* orow = out + (size_t)row*CC;
    orow[t]     = roundtf((v0-mean)*rstd*g[t]     + b[t]);
    orow[t+128] = roundtf((v1-mean)*rstd*g[t+128] + b[t+128]);
    orow[t+256] = roundtf((v2-mean)*rstd*g[t+256] + b[t+256]);
}

// ---------------- tf32 tensor-core GEMM (operands pre-rounded; no CVT in loop) ----
// out[m,n] = sum_k A[m,k]*B[k,n]
// EPI: 0=QKV split -> q/k/v [B,H,T,D]; 1=proj(+bias+res); 2=fc1(+bias,relu,round); 3=fc2(+bias,acc)
template<int EPI>
__global__ __launch_bounds__(256, 2)
void gemm_tc(const float* __restrict__ A, const float* __restrict__ Bw,
             const float* __restrict__ bias, const float* __restrict__ res,
             float* __restrict__ out, float* __restrict__ out_k, float* __restrict__ out_v,
             int K, int N)
{
    extern __shared__ float smem[];
    uint32_t smem_u32 = (uint32_t)__cvta_generic_to_shared(smem);

    const int tid  = threadIdx.x;
    const int bm   = blockIdx.y * BM;
    const int bn   = blockIdx.x * BN;
    const int warp = tid >> 5, lane = tid & 31;
    const int wm   = (warp >> 1) * 32;
    const int wn   = (warp & 1)  * 64;
    const int gid  = lane >> 2, tig = lane & 3;

    const int a_r0 = tid >> 3;
    const int a_c  = (tid & 7) * 4;
    const int b_k0 = tid >> 5;
    const int b_c  = (tid & 31) * 4;

    float acc[2][8][4];
    #pragma unroll
    for (int mt = 0; mt < 2; mt++)
        #pragma unroll
        for (int nt = 0; nt < 8; nt++)
            #pragma unroll
            for (int r = 0; r < 4; r++) acc[mt][nt][r] = 0.f;

    auto load_tile = [&](int k0, int buf) {
        #pragma unroll
        for (int i = 0; i < 4; i++) {
            int row = a_r0 + i*32;
            uint32_t s = smem_u32 + (uint32_t)(buf*A_BUF + row*ASTR + a_c)*4u;
            cp_async16(s, A + (size_t)(bm + row)*K + k0 + a_c);
        }
        #pragma unroll
        for (int i = 0; i < 4; i++) {
            int kr = b_k0 + i*8;
            uint32_t s = smem_u32 + (uint32_t)(2*A_BUF + buf*B_BUF + kr*BSTR + b_c)*4u;
            cp_async16(s, Bw + (size_t)(k0 + kr)*N + bn + b_c);
        }
        cp_commit();
    };

    const int ntiles = K / BK;
    load_tile(0, 0);

    for (int kt = 0; kt < ntiles; kt++) {
        int cur = kt & 1;
        if (kt + 1 < ntiles) { load_tile((kt+1)*BK, cur ^ 1); cp_wait<1>(); }
        else                 { cp_wait<0>(); }
        __syncthreads();

        const uint32_t* Ab = (const uint32_t*)(smem + cur*A_BUF);
        const uint32_t* Bb = (const uint32_t*)(smem + 2*A_BUF + cur*B_BUF);

        #pragma unroll
        for (int ks = 0; ks < 4; ks++) {
            const int k0 = ks * 8;
            uint32_t a[2][4];
            #pragma unroll
            for (int mt = 0; mt < 2; mt++) {
                const uint32_t* ap = Ab + (wm + mt*16 + gid)*ASTR + k0;
                a[mt][0] = ap[tig];
                a[mt][1] = ap[8*ASTR + tig];
                a[mt][2] = ap[tig + 4];
                a[mt][3] = ap[8*ASTR + tig + 4];
            }
            uint32_t b[8][2];
            #pragma unroll
            for (int nt = 0; nt < 8; nt++) {
                const uint32_t* bp = Bb + (k0 + tig)*BSTR + wn + nt*8 + gid;
                b[nt][0] = bp[0];
                b[nt][1] = bp[4*BSTR];
            }
            #pragma unroll
            for (int mt = 0; mt < 2; mt++)
                #pragma unroll
                for (int nt = 0; nt < 8; nt++)
                    asm volatile(
                        "mma.sync.aligned.m16n8k8.row.col.f32.tf32.tf32.f32 "
                        "{%0,%1,%2,%3}, {%4,%5,%6,%7}, {%8,%9}, {%0,%1,%2,%3};"
                        : "+f"(acc[mt][nt][0]), "+f"(acc[mt][nt][1]),
                          "+f"(acc[mt][nt][2]), "+f"(acc[mt][nt][3])
                        : "r"(a[mt][0]), "r"(a[mt][1]), "r"(a[mt][2]), "r"(a[mt][3]),
                          "r"(b[nt][0]), "r"(b[nt][1]));
        }
        __syncthreads();
    }

    // epilogue: c0=(gid,2tig) c1=(gid,2tig+1) c2=(gid+8,2tig) c3=(gid+8,2tig+1)
    #pragma unroll
    for (int mt = 0; mt < 2; mt++) {
        #pragma unroll
        for (int nt = 0; nt < 8; nt++) {
            #pragma unroll
            for (int r = 0; r < 4; r++) {
                int row = bm + wm + mt*16 + gid + ((r >= 2) ? 8 : 0);
                int col = bn + wn + nt*8 + tig*2 + (r & 1);
                float v = acc[mt][nt][r];
                if (EPI == 0) {
                    int src = col / CC, within = col % CC;
                    int h = within >> 6, d = within & 63;
                    float* dst = (src == 0) ? out : (src == 1) ? out_k : out_v;
                    dst[(((size_t)(row / TT)*HH + h)*TT + (row % TT))*DD + d] = v;
                } else if (EPI == 1) {
                    v += bias[col] + res[(size_t)row*N + col];
                    out[(size_t)row*N + col] = v;
                } else if (EPI == 2) {
                    v = roundtf(fmaxf(v + bias[col], 0.f));
                    out[(size_t)row*N + col] = v;
                } else {
                    out[(size_t)row*N + col] += v + bias[col];
                }
            }
        }
    }
}

// ---------------- causal attention (online softmax, one row/thread) ----------------
__global__ __launch_bounds__(256)
void attn_kernel(const float* __restrict__ q, const float* __restrict__ k,
                 const float* __restrict__ v, float* __restrict__ out)
{
    extern __shared__ float smem[];
    float* Ks = smem;
    float* Vs = smem + TT*DD;

    int bh = blockIdx.x;
    int b  = bh / HH;
    int h  = bh % HH;
    int tid = threadIdx.x;

    const float* kb = k + (size_t)bh * TT * DD;
    const float* vb = v + (size_t)bh * TT * DD;

    for (int i = tid*4; i < TT*DD; i += 256*4) {
        *(float4*)&Ks[i] = *(const float4*)&kb[i];
        *(float4*)&Vs[i] = *(const float4*)&vb[i];
    }

    float qr[64];
    const float* qp = q + (size_t)bh * TT * DD + (size_t)tid * DD;
    #pragma unroll
    for (int i = 0; i < 16; i++)
        *(float4*)&qr[i*4] = *(const float4*)&qp[i*4];

    __syncthreads();

    float o[64];
    #pragma unroll
    for (int d = 0; d < 64; d++) o[d] = 0.f;
    float mx = -1e30f, l = 0.f;
    const float scale = rsqrtf((float)CC);

    for (int j = 0; j <= tid; j++) {
        float s = 0.f;
        const float* kr = &Ks[j*64];
        #pragma unroll
        for (int d = 0; d < 64; d++) s += qr[d] * kr[d];
        s *= scale;
        float mn = fmaxf(mx, s);
        float c  = __expf(mx - mn);
        float p  = __expf(s  - mn);
        l = l * c + p;
        const float* vr = &Vs[j*64];
        #pragma unroll
        for (int d = 0; d < 64; d++) o[d] = o[d]*c + p*vr[d];
        mx = mn;
    }

    float inv = 1.f / l;
    float* op = out + ((size_t)b*TT + tid)*CC + h*DD;
    #pragma unroll
    for (int d = 0; d < 64; d++) op[d] = roundtf(o[d]*inv);
}

// ---------------- launch ----------------
extern "C" void kernel_launch(void* const* d_in, const int* in_sizes, int n_in,
                              void* d_out, int out_size)
{
    const float* x      = (const float*)d_in[0];
    const float* wq     = (const float*)d_in[1];
    const float* wk     = (const float*)d_in[2];
    const float* wv     = (const float*)d_in[3];
    const float* w_proj = (const float*)d_in[4];
    const float* b_proj = (const float*)d_in[5];
    const float* w1     = (const float*)d_in[6];
    const float* b1     = (const float*)d_in[7];
    const float* w2     = (const float*)d_in[8];
    const float* b2     = (const float*)d_in[9];
    const float* ln1_g  = (const float*)d_in[10];
    const float* ln1_b  = (const float*)d_in[11];
    const float* ln2_g  = (const float*)d_in[12];
    const float* ln2_b  = (const float*)d_in[13];
    float* out = (float*)d_out;

    void* p;
    cudaGetSymbolAddress(&p, g_h);      float* h     = (float*)p;
    cudaGetSymbolAddress(&p, g_q);      float* q     = (float*)p;
    cudaGetSymbolAddress(&p, g_k);      float* k     = (float*)p;
    cudaGetSymbolAddress(&p, g_v);      float* v     = (float*)p;
    cudaGetSymbolAddress(&p, g_attn);   float* attn  = (float*)p;
    cudaGetSymbolAddress(&p, g_hidden); float* hid   = (float*)p;
    cudaGetSymbolAddress(&p, g_w_qkv);  float* wqkv  = (float*)p;
    cudaGetSymbolAddress(&p, g_w_proj); float* wprj  = (float*)p;
    cudaGetSymbolAddress(&p, g_w1);     float* ww1   = (float*)p;
    cudaGetSymbolAddress(&p, g_w2);     float* ww2   = (float*)p;

    const int ATTN_SMEM = 2 * TT * DD * sizeof(float);
    cudaFuncSetAttribute(attn_kernel, cudaFuncAttributeMaxDynamicSharedMemorySize, ATTN_SMEM);
    cudaFuncSetAttribute(gemm_tc<0>, cudaFuncAttributeMaxDynamicSharedMemorySize, GEMM_SMEM_BYTES);
    cudaFuncSetAttribute(gemm_tc<1>, cudaFuncAttributeMaxDynamicSharedMemorySize, GEMM_SMEM_BYTES);
    cudaFuncSetAttribute(gemm_tc<2>, cudaFuncAttributeMaxDynamicSharedMemorySize, GEMM_SMEM_BYTES);
    cudaFuncSetAttribute(gemm_tc<3>, cudaFuncAttributeMaxDynamicSharedMemorySize, GEMM_SMEM_BYTES);

    // 0. weight packing (tf32 pre-round)
    pack_qkv<<<(CC*NQKV + 255)/256, 256>>>(wq, wk, wv, wqkv);
    pack_rnd<<<(CC*CC   + 255)/256, 256>>>(w_proj, wprj, CC*CC);
    pack_rnd<<<(CC*HID  + 255)/256, 256>>>(w1, ww1, CC*HID);
    pack_rnd<<<(HID*CC  + 255)/256, 256>>>(w2, ww2, HID*CC);

    // 1. LN1 -> h (tf32-rounded)
    ln_kernel<<<MM, 128>>>(x, ln1_g, ln1_b, h);

    // 2. fused QKV: [M,384] x [384,1152] -> q,k,v
    gemm_tc<0><<<dim3(NQKV/BN, MM/BM), 256, GEMM_SMEM_BYTES>>>(h, wqkv, nullptr, nullptr, q, k, v, CC, NQKV);

    // 3. causal attention -> attn (tf32-rounded)
    attn_kernel<<<BB*HH, 256, ATTN_SMEM>>>(q, k, v, attn);

    // 4. proj + bias + residual(x) -> d_out
    gemm_tc<1><<<dim3(CC/BN, MM/BM), 256, GEMM_SMEM_BYTES>>>(attn, wprj, b_proj, x, out, nullptr, nullptr, CC, CC);

    // 5. LN2 -> h (tf32-rounded)
    ln_kernel<<<MM, 128>>>(out, ln2_g, ln2_b, h);

    // 6. fc1 + bias + relu -> hidden (tf32-rounded)
    gemm_tc<2><<<dim3(HID/BN, MM/BM), 256, GEMM_SMEM_BYTES>>>(h, ww1, b1, nullptr, hid, nullptr, nullptr, CC, HID);

    // 7. fc2 + bias, accumulate into d_out
    gemm_tc<3><<<dim3(CC/BN, MM/BM), 256, GEMM_SMEM_BYTES>>>(hid, ww2, b2, nullptr, out, nullptr, nullptr, HID, CC);
}

// round 7
// speedup vs baseline: 2.6529x; 1.1053x over previous
#include <cuda_runtime.h>
#include <cuda_fp16.h>
#include <cstdint>

#define BB   128
#define TT   256
#define CC   384
#define HH   6
#define DD   64
#define HID  1536
#define MM   (BB*TT)   // 32768
#define NQKV 1152

// GEMM tiling (fp16 operands, fp32 accum)
#define BM 128
#define BN 128
#define BK 32
#define ASTR 40                       // halves per row (80B) — conflict-free
#define A_BUF_H (BM*ASTR)             // 5120 halves
#define B_BUF_H (BN*ASTR)             // 5120 halves
#define STG_H   (A_BUF_H + B_BUF_H)   // 10240 halves per stage
#define GEMM_SMEM_BYTES (2*STG_H*2)   // 40960 B

// ---------------- scratch (alloc-free: __device__ globals) ----------------
__device__ __half g_h[(size_t)MM*CC];
__device__ float  g_q[(size_t)BB*HH*TT*DD];
__device__ float  g_k[(size_t)BB*HH*TT*DD];
__device__ float  g_v[(size_t)BB*HH*TT*DD];
__device__ __half g_attn[(size_t)MM*CC];
__device__ __half g_hidden[(size_t)MM*HID];
// fp16 weights, [n][k] layout
__device__ __half g_w_qkv[(size_t)NQKV*CC];
__device__ __half g_w_proj[(size_t)CC*CC];
__device__ __half g_w1[(size_t)HID*CC];
__device__ __half g_w2[(size_t)CC*HID];

// ---------------- helpers ----------------
__device__ __forceinline__ void cp_async16(uint32_t s, const void* g) {
    asm volatile("cp.async.cg.shared.global [%0], [%1], 16;\n" :: "r"(s), "l"(g));
}
__device__ __forceinline__ void cp_commit() {
    asm volatile("cp.async.commit_group;\n");
}
template<int N> __device__ __forceinline__ void cp_wait() {
    asm volatile("cp.async.wait_group %0;\n" :: "n"(N));
}

// ---------------- fused weight pack: transpose to [n][k] fp16 ----------------
#define P_QKV  (CC*NQKV)              // 442368
#define P_PRJ  (CC*CC)                // 147456
#define P_W1   (CC*HID)               // 589824
#define P_W2   (HID*CC)               // 589824
#define P_TOT  (P_QKV + P_PRJ + P_W1 + P_W2)

__global__ void pack_all(const float* __restrict__ wq, const float* __restrict__ wk,
                         const float* __restrict__ wv, const float* __restrict__ wp,
                         const float* __restrict__ w1, const float* __restrict__ w2,
                         __half* __restrict__ oqkv, __half* __restrict__ oprj,
                         __half* __restrict__ ow1, __half* __restrict__ ow2)
{
    int idx = blockIdx.x * blockDim.x + threadIdx.x;
    if (idx >= P_TOT) return;
    if (idx < P_QKV) {
        int n = idx / CC, k = idx % CC;
        int src = n / CC, within = n % CC;
        int h = within >> 6, d = within & 63;
        const float* w = (src == 0) ? wq : (src == 1) ? wk : wv;
        oqkv[idx] = __float2half(w[((size_t)h*CC + k)*DD + d]);
    } else if (idx < P_QKV + P_PRJ) {
        int i = idx - P_QKV;
        int n = i / CC, k = i % CC;
        oprj[i] = __float2half(wp[(size_t)k*CC + n]);
    } else if (idx < P_QKV + P_PRJ + P_W1) {
        int i = idx - P_QKV - P_PRJ;
        int n = i / CC, k = i % CC;          // n < 1536
        ow1[i] = __float2half(w1[(size_t)k*HID + n]);
    } else {
        int i = idx - P_QKV - P_PRJ - P_W1;
        int n = i / HID, k = i % HID;        // n < 384, k < 1536
        ow2[i] = __float2half(w2[(size_t)k*CC + n]);
    }
}

// ---------------- layernorm (fp16 output) ----------------
__global__ void ln_kernel(const float* __restrict__ x, const float* __restrict__ g,
                          const float* __restrict__ b, __half* __restrict__ out)
{
    int row = blockIdx.x;
    const float* xr = x + (size_t)row*CC;
    int t = threadIdx.x;
    float v0 = xr[t], v1 = xr[t+128], v2 = xr[t+256];
    float s  = v0+v1+v2;
    float ss = v0*v0 + v1*v1 + v2*v2;
    #pragma unroll
    for (int o = 16; o > 0; o >>= 1) {
        s  += __shfl_xor_sync(0xffffffffu, s,  o);
        ss += __shfl_xor_sync(0xffffffffu, ss, o);
    }
    __shared__ float sh_s[4], sh_ss[4];
    int w = t >> 5, lane = t & 31;
    if (lane == 0) { sh_s[w] = s; sh_ss[w] = ss; }
    __syncthreads();
    s  = sh_s[0]  + sh_s[1]  + sh_s[2]  + sh_s[3];
    ss = sh_ss[0] + sh_ss[1] + sh_ss[2] + sh_ss[3];
    float mean = s * (1.f/CC);
    float var  = ss * (1.f/CC) - mean*mean;
    float rstd = rsqrtf(var + 1e-5f);
    __half* orow = out + (size_t)row*CC;
    orow[t]     = __float2half((v0-mean)*rstd*g[t]     + b[t]);
    orow[t+128] = __float2half((v1-mean)*rstd*g[t+128] + b[t+128]);
    orow[t+256] = __float2half((v2-mean)*rstd*g[t+256] + b[t+256]);
}

// ---------------- fp16 tensor-core GEMM, fp32 accumulate ----------------
// out[m,n] = sum_k A[m,k]*B[n,k]   (B pre-transposed)
// EPI: 0=QKV split -> q/k/v fp32 [B,H,T,D]; 1=proj(+bias+res)->f32; 2=fc1(relu)->fp16; 3=fc2(+bias,acc)->f32
template<int EPI>
__global__ __launch_bounds__(256, 2)
void gemm_f16(const __half* __restrict__ A, const __half* __restrict__ Bw,
              const float* __restrict__ bias, const float* __restrict__ res,
              float* __restrict__ outf, float* __restrict__ out_k, float* __restrict__ out_v,
              __half* __restrict__ outh, int K, int N)
{
    extern __shared__ __half smh[];
    uint32_t smem_u32 = (uint32_t)__cvta_generic_to_shared(smh);

    const int tid  = threadIdx.x;
    const int bm   = blockIdx.y * BM;
    const int bn   = blockIdx.x * BN;
    const int warp = tid >> 5, lane = tid & 31;
    const int wm   = (warp >> 1) * 32;
    const int wn   = (warp & 1)  * 64;
    const int gid  = lane >> 2, tig = lane & 3;

    float acc[2][8][4];
    #pragma unroll
    for (int mt = 0; mt < 2; mt++)
        #pragma unroll
        for (int nt = 0; nt < 8; nt++)
            #pragma unroll
            for (int r = 0; r < 4; r++) acc[mt][nt][r] = 0.f;

    // global tile load: 128 rows x 32 halves = 512 chunks of 16B per matrix; 2/thread
    auto load_tile = [&](int k0, int buf) {
        #pragma unroll
        for (int i = 0; i < 2; i++) {
            int c = tid + i*256;
            int row = c >> 2, co = (c & 3) * 8;
            uint32_t s = smem_u32 + (uint32_t)(buf*STG_H + row*ASTR + co)*2u;
            cp_async16(s, A + (size_t)(bm + row)*K + k0 + co);
        }
        #pragma unroll
        for (int i = 0; i < 2; i++) {
            int c = tid + i*256;
            int row = c >> 2, co = (c & 3) * 8;
            uint32_t s = smem_u32 + (uint32_t)(buf*STG_H + A_BUF_H + row*ASTR + co)*2u;
            cp_async16(s, Bw + (size_t)(bn + row)*K + k0 + co);
        }
        cp_commit();
    };

    const int ntiles = K / BK;
    load_tile(0, 0);

    for (int kt = 0; kt < ntiles; kt++) {
        int cur = kt & 1;
        if (kt + 1 < ntiles) { load_tile((kt+1)*BK, cur ^ 1); cp_wait<1>(); }
        else                 { cp_wait<0>(); }
        __syncthreads();

        const __half* Ab = smh + cur*STG_H;
        const __half* Bb = Ab + A_BUF_H;

        #pragma unroll
        for (int ks = 0; ks < 2; ks++) {
            const int k0 = ks * 16;
            // A frags: a0=(gid, k0+2tig) a1=(gid+8, ..) a2=(gid, k0+2tig+8) a3=(gid+8, ..+8)
            uint32_t a[2][4];
            #pragma unroll
            for (int mt = 0; mt < 2; mt++) {
                const __half* ap = Ab + (wm + mt*16 + gid)*ASTR + k0 + 2*tig;
                a[mt][0] = *(const uint32_t*)(ap);
                a[mt][1] = *(const uint32_t*)(ap + 8*ASTR);
                a[mt][2] = *(const uint32_t*)(ap + 8);
                a[mt][3] = *(const uint32_t*)(ap + 8*ASTR + 8);
            }
            // B frags: b0=(k0+2tig, n=gid) b1=(k0+2tig+8, n=gid); Bs is [n][k]
            uint32_t b[8][2];
            #pragma unroll
            for (int nt = 0; nt < 8; nt++) {
                const __half* bp = Bb + (wn + nt*8 + gid)*ASTR + k0 + 2*tig;
                b[nt][0] = *(const uint32_t*)(bp);
                b[nt][1] = *(const uint32_t*)(bp + 8);
            }
            #pragma unroll
            for (int mt = 0; mt < 2; mt++)
                #pragma unroll
                for (int nt = 0; nt < 8; nt++)
                    asm volatile(
                        "mma.sync.aligned.m16n8k16.row.col.f32.f16.f16.f32 "
                        "{%0,%1,%2,%3}, {%4,%5,%6,%7}, {%8,%9}, {%0,%1,%2,%3};"
                        : "+f"(acc[mt][nt][0]), "+f"(acc[mt][nt][1]),
                          "+f"(acc[mt][nt][2]), "+f"(acc[mt][nt][3])
                        : "r"(a[mt][0]), "r"(a[mt][1]), "r"(a[mt][2]), "r"(a[mt][3]),
                          "r"(b[nt][0]), "r"(b[nt][1]));
        }
        __syncthreads();
    }

    // epilogue: c0=(gid,2tig) c1=(gid,2tig+1) c2=(gid+8,2tig) c3=(gid+8,2tig+1)
    #pragma unroll
    for (int mt = 0; mt < 2; mt++) {
        #pragma unroll
        for (int nt = 0; nt < 8; nt++) {
            #pragma unroll
            for (int r = 0; r < 4; r++) {
                int row = bm + wm + mt*16 + gid + ((r >= 2) ? 8 : 0);
                int col = bn + wn + nt*8 + tig*2 + (r & 1);
                float v = acc[mt][nt][r];
                if (EPI == 0) {
                    int src = col / CC, within = col % CC;
                    int h = within >> 6, d = within & 63;
                    float* dst = (src == 0) ? outf : (src == 1) ? out_k : out_v;
                    dst[(((size_t)(row / TT)*HH + h)*TT + (row % TT))*DD + d] = v;
                } else if (EPI == 1) {
                    v += bias[col] + res[(size_t)row*N + col];
                    outf[(size_t)row*N + col] = v;
                } else if (EPI == 2) {
                    outh[(size_t)row*N + col] = __float2half(fmaxf(v + bias[col], 0.f));
                } else {
                    outf[(size_t)row*N + col] += v + bias[col];
                }
            }
        }
    }
}

// ---------------- causal attention (fp32 math, fp16 output) ----------------
__global__ __launch_bounds__(256)
void attn_kernel(const float* __restrict__ q, const float* __restrict__ k,
                 const float* __restrict__ v, __half* __restrict__ out)
{
    extern __shared__ float smem[];
    float* Ks = smem;
    float* Vs = smem + TT*DD;

    int bh = blockIdx.x;
    int b  = bh / HH;
    int h  = bh % HH;
    int tid = threadIdx.x;

    const float* kb = k + (size_t)bh * TT * DD;
    const float* vb = v + (size_t)bh * TT * DD;

    for (int i = tid*4; i < TT*DD; i += 256*4) {
        *(float4*)&Ks[i] = *(const float4*)&kb[i];
        *(float4*)&Vs[i] = *(const float4*)&vb[i];
    }

    float qr[64];
    const float* qp = q + (size_t)bh * TT * DD + (size_t)tid * DD;
    #pragma unroll
    for (int i = 0; i < 16; i++)
        *(float4*)&qr[i*4] = *(const float4*)&qp[i*4];

    __syncthreads();

    float o[64];
    #pragma unroll
    for (int d = 0; d < 64; d++) o[d] = 0.f;
    float mx = -1e30f, l = 0.f;
    const float scale = rsqrtf((float)CC);

    for (int j = 0; j <= tid; j++) {
        float s = 0.f;
        const float* kr = &Ks[j*64];
        #pragma unroll
        for (int d = 0; d < 64; d++) s += qr[d] * kr[d];
        s *= scale;
        float mn = fmaxf(mx, s);
        float c  = __expf(mx - mn);
        float p  = __expf(s  - mn);
        l = l * c + p;
        const float* vr = &Vs[j*64];
        #pragma unroll
        for (int d = 0; d < 64; d++) o[d] = o[d]*c + p*vr[d];
        mx = mn;
    }

    float inv = 1.f / l;
    __half* op = out + ((size_t)b*TT + tid)*CC + h*DD;
    #pragma unroll
    for (int d = 0; d < 64; d++) op[d] = __float2half(o[d]*inv);
}

// ---------------- launch ----------------
extern "C" void kernel_launch(void* const* d_in, const int* in_sizes, int n_in,
                              void* d_out, int out_size)
{
    const float* x      = (const float*)d_in[0];
    const float* wq     = (const float*)d_in[1];
    const float* wk     = (const float*)d_in[2];
    const float* wv     = (const float*)d_in[3];
    const float* w_proj = (const float*)d_in[4];
    const float* b_proj = (const float*)d_in[5];
    const float* w1     = (const float*)d_in[6];
    const float* b1     = (const float*)d_in[7];
    const float* w2     = (const float*)d_in[8];
    const float* b2     = (const float*)d_in[9];
    const float* ln1_g  = (const float*)d_in[10];
    const float* ln1_b  = (const float*)d_in[11];
    const float* ln2_g  = (const float*)d_in[12];
    const float* ln2_b  = (const float*)d_in[13];
    float* out = (float*)d_out;

    void* p;
    cudaGetSymbolAddress(&p, g_h);      __half* h     = (__half*)p;
    cudaGetSymbolAddress(&p, g_q);      float*  q     = (float*)p;
    cudaGetSymbolAddress(&p, g_k);      float*  k     = (float*)p;
    cudaGetSymbolAddress(&p, g_v);      float*  v     = (float*)p;
    cudaGetSymbolAddress(&p, g_attn);   __half* attn  = (__half*)p;
    cudaGetSymbolAddress(&p, g_hidden); __half* hid   = (__half*)p;
    cudaGetSymbolAddress(&p, g_w_qkv);  __half* wqkv  = (__half*)p;
    cudaGetSymbolAddress(&p, g_w_proj); __half* wprj  = (__half*)p;
    cudaGetSymbolAddress(&p, g_w1);     __half* ww1   = (__half*)p;
    cudaGetSymbolAddress(&p, g_w2);     __half* ww2   = (__half*)p;

    const int ATTN_SMEM = 2 * TT * DD * sizeof(float);
    cudaFuncSetAttribute(attn_kernel, cudaFuncAttributeMaxDynamicSharedMemorySize, ATTN_SMEM);
    cudaFuncSetAttribute(gemm_f16<0>, cudaFuncAttributeMaxDynamicSharedMemorySize, GEMM_SMEM_BYTES);
    cudaFuncSetAttribute(gemm_f16<1>, cudaFuncAttributeMaxDynamicSharedMemorySize, GEMM_SMEM_BYTES);
    cudaFuncSetAttribute(gemm_f16<2>, cudaFuncAttributeMaxDynamicSharedMemorySize, GEMM_SMEM_BYTES);
    cudaFuncSetAttribute(gemm_f16<3>, cudaFuncAttributeMaxDynamicSharedMemorySize, GEMM_SMEM_BYTES);

    // 0. fused weight pack (fp16, [n][k])
    pack_all<<<(P_TOT + 255)/256, 256>>>(wq, wk, wv, w_proj, w1, w2, wqkv, wprj, ww1, ww2);

    // 1. LN1 -> h (fp16)
    ln_kernel<<<MM, 128>>>(x, ln1_g, ln1_b, h);

    // 2. fused QKV: [M,384] x [1152,384]^T -> q,k,v (fp32)
    gemm_f16<0><<<dim3(NQKV/BN, MM/BM), 256, GEMM_SMEM_BYTES>>>(h, wqkv, nullptr, nullptr, q, k, v, nullptr, CC, NQKV);

    // 3. causal attention -> attn (fp16)
    attn_kernel<<<BB*HH, 256, ATTN_SMEM>>>(q, k, v, attn);

    // 4. proj + bias + residual(x) -> d_out (fp32)
    gemm_f16<1><<<dim3(CC/BN, MM/BM), 256, GEMM_SMEM_BYTES>>>(attn, wprj, b_proj, x, out, nullptr, nullptr, nullptr, CC, CC);

    // 5. LN2 -> h (fp16)
    ln_kernel<<<MM, 128>>>(out, ln2_g, ln2_b, h);

    // 6. fc1 + bias + relu -> hidden (fp16)
    gemm_f16<2><<<dim3(HID/BN, MM/BM), 256, GEMM_SMEM_BYTES>>>(h, ww1, b1, nullptr, nullptr, nullptr, nullptr, hid, CC, HID);

    // 7. fc2 + bias, accumulate into d_out (fp32)
    gemm_f16<3><<<dim3(CC/BN, MM/BM), 256, GEMM_SMEM_BYTES>>>(hid, ww2, b2, nullptr, out, nullptr, nullptr, nullptr, HID, CC);
}

// round 8
// speedup vs baseline: 4.6924x; 1.7688x over previous
#include <cuda_runtime.h>
#include <cuda_fp16.h>
#include <cstdint>

#define BB   128
#define TT   256
#define CC   384
#define HH   6
#define DD   64
#define HID  1536
#define MM   (BB*TT)   // 32768
#define NQKV 1152

// GEMM tiling (fp16 operands, fp32 accum)
#define BM 128
#define BN 128
#define BK 32
#define ASTR 40
#define A_BUF_H (BM*ASTR)
#define B_BUF_H (BN*ASTR)
#define STG_H   (A_BUF_H + B_BUF_H)
#define GEMM_SMEM_BYTES (2*STG_H*2)   // 40960 B

// attention smem strides (halves) — conflict-free
#define KSTR 72
#define VSTR 264
#define ATTN_SMEM_B ((TT*KSTR + DD*VSTR)*2)   // 70656

// ---------------- scratch ----------------
__device__ __half g_h[(size_t)MM*CC];
__device__ __half g_q[(size_t)BB*HH*TT*DD];
__device__ __half g_k[(size_t)BB*HH*TT*DD];
__device__ __half g_vt[(size_t)BB*HH*DD*TT];   // V transposed [b,h,d,t]
__device__ __half g_attn[(size_t)MM*CC];
__device__ __half g_hidden[(size_t)MM*HID];
__device__ __half g_w_qkv[(size_t)NQKV*CC];
__device__ __half g_w_proj[(size_t)CC*CC];
__device__ __half g_w1[(size_t)HID*CC];
__device__ __half g_w2[(size_t)CC*HID];

// ---------------- helpers ----------------
__device__ __forceinline__ void cp_async16(uint32_t s, const void* g) {
    asm volatile("cp.async.cg.shared.global [%0], [%1], 16;\n" :: "r"(s), "l"(g));
}
__device__ __forceinline__ void cp_commit() {
    asm volatile("cp.async.commit_group;\n");
}
template<int N> __device__ __forceinline__ void cp_wait() {
    asm volatile("cp.async.wait_group %0;\n" :: "n"(N));
}
__device__ __forceinline__ void mma16816(float* c, const uint32_t* a, const uint32_t* b) {
    asm volatile(
        "mma.sync.aligned.m16n8k16.row.col.f32.f16.f16.f32 "
        "{%0,%1,%2,%3}, {%4,%5,%6,%7}, {%8,%9}, {%0,%1,%2,%3};"
        : "+f"(c[0]), "+f"(c[1]), "+f"(c[2]), "+f"(c[3])
        : "r"(a[0]), "r"(a[1]), "r"(a[2]), "r"(a[3]), "r"(b[0]), "r"(b[1]));
}

// ---------------- fused weight pack ----------------
#define P_QKV  (CC*NQKV)
#define P_PRJ  (CC*CC)
#define P_W1   (CC*HID)
#define P_W2   (HID*CC)
#define P_TOT  (P_QKV + P_PRJ + P_W1 + P_W2)

__global__ void pack_all(const float* __restrict__ wq, const float* __restrict__ wk,
                         const float* __restrict__ wv, const float* __restrict__ wp,
                         const float* __restrict__ w1, const float* __restrict__ w2,
                         __half* __restrict__ oqkv, __half* __restrict__ oprj,
                         __half* __restrict__ ow1, __half* __restrict__ ow2)
{
    int idx = blockIdx.x * blockDim.x + threadIdx.x;
    if (idx >= P_TOT) return;
    if (idx < P_QKV) {
        int n = idx / CC, k = idx % CC;
        int src = n / CC, within = n % CC;
        int h = within >> 6, d = within & 63;
        const float* w = (src == 0) ? wq : (src == 1) ? wk : wv;
        oqkv[idx] = __float2half(w[((size_t)h*CC + k)*DD + d]);
    } else if (idx < P_QKV + P_PRJ) {
        int i = idx - P_QKV;
        int n = i / CC, k = i % CC;
        oprj[i] = __float2half(wp[(size_t)k*CC + n]);
    } else if (idx < P_QKV + P_PRJ + P_W1) {
        int i = idx - P_QKV - P_PRJ;
        int n = i / CC, k = i % CC;
        ow1[i] = __float2half(w1[(size_t)k*HID + n]);
    } else {
        int i = idx - P_QKV - P_PRJ - P_W1;
        int n = i / HID, k = i % HID;
        ow2[i] = __float2half(w2[(size_t)k*CC + n]);
    }
}

// ---------------- layernorm (fp16 output) ----------------
__global__ void ln_kernel(const float* __restrict__ x, const float* __restrict__ g,
                          const float* __restrict__ b, __half* __restrict__ out)
{
    int row = blockIdx.x;
    const float* xr = x + (size_t)row*CC;
    int t = threadIdx.x;
    float v0 = xr[t], v1 = xr[t+128], v2 = xr[t+256];
    float s  = v0+v1+v2;
    float ss = v0*v0 + v1*v1 + v2*v2;
    #pragma unroll
    for (int o = 16; o > 0; o >>= 1) {
        s  += __shfl_xor_sync(0xffffffffu, s,  o);
        ss += __shfl_xor_sync(0xffffffffu, ss, o);
    }
    __shared__ float sh_s[4], sh_ss[4];
    int w = t >> 5, lane = t & 31;
    if (lane == 0) { sh_s[w] = s; sh_ss[w] = ss; }
    __syncthreads();
    s  = sh_s[0]  + sh_s[1]  + sh_s[2]  + sh_s[3];
    ss = sh_ss[0] + sh_ss[1] + sh_ss[2] + sh_ss[3];
    float mean = s * (1.f/CC);
    float var  = ss * (1.f/CC) - mean*mean;
    float rstd = rsqrtf(var + 1e-5f);
    __half* orow = out + (size_t)row*CC;
    orow[t]     = __float2half((v0-mean)*rstd*g[t]     + b[t]);
    orow[t+128] = __float2half((v1-mean)*rstd*g[t+128] + b[t+128]);
    orow[t+256] = __float2half((v2-mean)*rstd*g[t+256] + b[t+256]);
}

// ---------------- fp16 tensor-core GEMM ----------------
// EPI: 0=QKV split -> q/k fp16 [B,H,T,D], v fp16 transposed [B,H,D,T]
//      1=proj(+bias+res)->f32; 2=fc1(relu)->fp16; 3=fc2(+bias,acc)->f32
template<int EPI>
__global__ __launch_bounds__(256, 2)
void gemm_f16(const __half* __restrict__ A, const __half* __restrict__ Bw,
              const float* __restrict__ bias, const float* __restrict__ res,
              float* __restrict__ outf, __half* __restrict__ outh,
              __half* __restrict__ out_k, __half* __restrict__ out_v,
              int K, int N)
{
    extern __shared__ __half smh[];
    uint32_t smem_u32 = (uint32_t)__cvta_generic_to_shared(smh);

    const int tid  = threadIdx.x;
    const int bm   = blockIdx.y * BM;
    const int bn   = blockIdx.x * BN;
    const int warp = tid >> 5, lane = tid & 31;
    const int wm   = (warp >> 1) * 32;
    const int wn   = (warp & 1)  * 64;
    const int gid  = lane >> 2, tig = lane & 3;

    float acc[2][8][4];
    #pragma unroll
    for (int mt = 0; mt < 2; mt++)
        #pragma unroll
        for (int nt = 0; nt < 8; nt++)
            #pragma unroll
            for (int r = 0; r < 4; r++) acc[mt][nt][r] = 0.f;

    auto load_tile = [&](int k0, int buf) {
        #pragma unroll
        for (int i = 0; i < 2; i++) {
            int c = tid + i*256;
            int row = c >> 2, co = (c & 3) * 8;
            uint32_t s = smem_u32 + (uint32_t)(buf*STG_H + row*ASTR + co)*2u;
            cp_async16(s, A + (size_t)(bm + row)*K + k0 + co);
        }
        #pragma unroll
        for (int i = 0; i < 2; i++) {
            int c = tid + i*256;
            int row = c >> 2, co = (c & 3) * 8;
            uint32_t s = smem_u32 + (uint32_t)(buf*STG_H + A_BUF_H + row*ASTR + co)*2u;
            cp_async16(s, Bw + (size_t)(bn + row)*K + k0 + co);
        }
        cp_commit();
    };

    const int ntiles = K / BK;
    load_tile(0, 0);

    for (int kt = 0; kt < ntiles; kt++) {
        int cur = kt & 1;
        if (kt + 1 < ntiles) { load_tile((kt+1)*BK, cur ^ 1); cp_wait<1>(); }
        else                 { cp_wait<0>(); }
        __syncthreads();

        const __half* Ab = smh + cur*STG_H;
        const __half* Bb = Ab + A_BUF_H;

        #pragma unroll
        for (int ks = 0; ks < 2; ks++) {
            const int k0 = ks * 16;
            uint32_t a[2][4];
            #pragma unroll
            for (int mt = 0; mt < 2; mt++) {
                const __half* ap = Ab + (wm + mt*16 + gid)*ASTR + k0 + 2*tig;
                a[mt][0] = *(const uint32_t*)(ap);
                a[mt][1] = *(const uint32_t*)(ap + 8*ASTR);
                a[mt][2] = *(const uint32_t*)(ap + 8);
                a[mt][3] = *(const uint32_t*)(ap + 8*ASTR + 8);
            }
            uint32_t b[8][2];
            #pragma unroll
            for (int nt = 0; nt < 8; nt++) {
                const __half* bp = Bb + (wn + nt*8 + gid)*ASTR + k0 + 2*tig;
                b[nt][0] = *(const uint32_t*)(bp);
                b[nt][1] = *(const uint32_t*)(bp + 8);
            }
            #pragma unroll
            for (int mt = 0; mt < 2; mt++)
                #pragma unroll
                for (int nt = 0; nt < 8; nt++)
                    mma16816(acc[mt][nt], a[mt], b[nt]);
        }
        __syncthreads();
    }

    #pragma unroll
    for (int mt = 0; mt < 2; mt++) {
        #pragma unroll
        for (int nt = 0; nt < 8; nt++) {
            #pragma unroll
            for (int r = 0; r < 4; r++) {
                int row = bm + wm + mt*16 + gid + ((r >= 2) ? 8 : 0);
                int col = bn + wn + nt*8 + tig*2 + (r & 1);
                float v = acc[mt][nt][r];
                if (EPI == 0) {
                    int src = col / CC, within = col % CC;
                    int h = within >> 6, d = within & 63;
                    int bidx = row / TT, t = row % TT;
                    if (src == 0)
                        outh[(((size_t)bidx*HH + h)*TT + t)*DD + d] = __float2half(v);
                    else if (src == 1)
                        out_k[(((size_t)bidx*HH + h)*TT + t)*DD + d] = __float2half(v);
                    else
                        out_v[(((size_t)bidx*HH + h)*DD + d)*TT + t] = __float2half(v);
                } else if (EPI == 1) {
                    outf[(size_t)row*N + col] = v + bias[col] + res[(size_t)row*N + col];
                } else if (EPI == 2) {
                    outh[(size_t)row*N + col] = __float2half(fmaxf(v + bias[col], 0.f));
                } else {
                    outf[(size_t)row*N + col] += v + bias[col];
                }
            }
        }
    }
}

// ---------------- tensor-core flash attention ----------------
// grid (half, h, b); 128 threads; warp w handles rows half*128 + w*32
__global__ __launch_bounds__(128, 2)
void attn_mma(const __half* __restrict__ q, const __half* __restrict__ k,
              const __half* __restrict__ vt, __half* __restrict__ out)
{
    extern __shared__ __half sm[];
    __half* Ks = sm;                 // [TT][KSTR]
    __half* Vs = sm + TT*KSTR;       // [DD][VSTR]
    uint32_t smemK = (uint32_t)__cvta_generic_to_shared(Ks);
    uint32_t smemV = (uint32_t)__cvta_generic_to_shared(Vs);

    const int half_ = blockIdx.x, hh = blockIdx.y, b = blockIdx.z;
    const int bh = b*HH + hh;
    const int tid = threadIdx.x, warp = tid >> 5, lane = tid & 31;
    const int gid = lane >> 2, tig = lane & 3;
    const int ntok = (half_ + 1) * 128;

    // stage K and Vt
    const __half* kg = k + (size_t)bh*TT*DD;
    for (int c = tid; c < ntok*8; c += 128) {
        int row = c >> 3, co = (c & 7)*8;
        cp_async16(smemK + (uint32_t)(row*KSTR + co)*2u, kg + row*DD + co);
    }
    const __half* vg = vt + (size_t)bh*DD*TT;
    const int vch = ntok >> 3;
    for (int c = tid; c < DD*vch; c += 128) {
        int d = c / vch, co = (c % vch)*8;
        cp_async16(smemV + (uint32_t)(d*VSTR + co)*2u, vg + d*TT + co);
    }
    cp_commit();

    // Q fragments from global
    const int rowbase = half_*128 + warp*32;
    const __half* qg = q + ((size_t)bh*TT + rowbase)*DD;
    uint32_t qf[2][4][4];
    #pragma unroll
    for (int mt = 0; mt < 2; mt++)
        #pragma unroll
        for (int f = 0; f < 4; f++) {
            const __half* p0 = qg + (mt*16 + gid)*DD + f*16 + 2*tig;
            qf[mt][f][0] = *(const uint32_t*)(p0);
            qf[mt][f][1] = *(const uint32_t*)(p0 + 8*DD);
            qf[mt][f][2] = *(const uint32_t*)(p0 + 8);
            qf[mt][f][3] = *(const uint32_t*)(p0 + 8*DD + 8);
        }

    float o[2][8][4];
    #pragma unroll
    for (int mt = 0; mt < 2; mt++)
        #pragma unroll
        for (int nt = 0; nt < 8; nt++)
            #pragma unroll
            for (int r = 0; r < 4; r++) o[mt][nt][r] = 0.f;
    float mrow[2][2] = {{-1e30f,-1e30f},{-1e30f,-1e30f}};
    float lrow[2][2] = {{0.f,0.f},{0.f,0.f}};
    const float scale = rsqrtf((float)CC);

    cp_wait<0>();
    __syncthreads();

    const int ntiles = (rowbase + 32 + 63) >> 6;
    for (int t = 0; t < ntiles; t++) {
        // S = Q @ K_tile^T
        float s[2][8][4];
        #pragma unroll
        for (int mt = 0; mt < 2; mt++)
            #pragma unroll
            for (int nt = 0; nt < 8; nt++)
                #pragma unroll
                for (int r = 0; r < 4; r++) s[mt][nt][r] = 0.f;

        #pragma unroll
        for (int f = 0; f < 4; f++) {
            uint32_t bf[8][2];
            #pragma unroll
            for (int nt = 0; nt < 8; nt++) {
                const __half* bp = Ks + (t*64 + nt*8 + gid)*KSTR + f*16 + 2*tig;
                bf[nt][0] = *(const uint32_t*)(bp);
                bf[nt][1] = *(const uint32_t*)(bp + 8);
            }
            #pragma unroll
            for (int mt = 0; mt < 2; mt++)
                #pragma unroll
                for (int nt = 0; nt < 8; nt++)
                    mma16816(s[mt][nt], qf[mt][f], bf[nt]);
        }

        // online softmax; P packed into pf
        uint32_t pf[2][4][4];
        #pragma unroll
        for (int mt = 0; mt < 2; mt++) {
            const int rA = rowbase + mt*16 + gid;
            const int rB = rA + 8;
            #pragma unroll
            for (int nt = 0; nt < 8; nt++) {
                int c0 = t*64 + nt*8 + 2*tig;
                if (c0     > rA) s[mt][nt][0] = -1e30f;
                if (c0 + 1 > rA) s[mt][nt][1] = -1e30f;
                if (c0     > rB) s[mt][nt][2] = -1e30f;
                if (c0 + 1 > rB) s[mt][nt][3] = -1e30f;
            }
            float mxA = -1e30f, mxB = -1e30f;
            #pragma unroll
            for (int nt = 0; nt < 8; nt++) {
                mxA = fmaxf(mxA, fmaxf(s[mt][nt][0], s[mt][nt][1]));
                mxB = fmaxf(mxB, fmaxf(s[mt][nt][2], s[mt][nt][3]));
            }
            mxA = fmaxf(mxA, __shfl_xor_sync(0xffffffffu, mxA, 1));
            mxA = fmaxf(mxA, __shfl_xor_sync(0xffffffffu, mxA, 2));
            mxB = fmaxf(mxB, __shfl_xor_sync(0xffffffffu, mxB, 1));
            mxB = fmaxf(mxB, __shfl_xor_sync(0xffffffffu, mxB, 2));

            float mnA = fmaxf(mrow[mt][0], mxA);
            float mnB = fmaxf(mrow[mt][1], mxB);
            float cA  = __expf(scale*(mrow[mt][0] - mnA));
            float cB  = __expf(scale*(mrow[mt][1] - mnB));
            mrow[mt][0] = mnA; mrow[mt][1] = mnB;

            float sA = 0.f, sB = 0.f;
            #pragma unroll
            for (int nt = 0; nt < 8; nt++) {
                s[mt][nt][0] = __expf(scale*(s[mt][nt][0] - mnA));
                s[mt][nt][1] = __expf(scale*(s[mt][nt][1] - mnA));
                s[mt][nt][2] = __expf(scale*(s[mt][nt][2] - mnB));
                s[mt][nt][3] = __expf(scale*(s[mt][nt][3] - mnB));
                sA += s[mt][nt][0] + s[mt][nt][1];
                sB += s[mt][nt][2] + s[mt][nt][3];
            }
            sA += __shfl_xor_sync(0xffffffffu, sA, 1);
            sA += __shfl_xor_sync(0xffffffffu, sA, 2);
            sB += __shfl_xor_sync(0xffffffffu, sB, 1);
            sB += __shfl_xor_sync(0xffffffffu, sB, 2);
            lrow[mt][0] = lrow[mt][0]*cA + sA;
            lrow[mt][1] = lrow[mt][1]*cB + sB;

            #pragma unroll
            for (int nt = 0; nt < 8; nt++) {
                o[mt][nt][0] *= cA; o[mt][nt][1] *= cA;
                o[mt][nt][2] *= cB; o[mt][nt][3] *= cB;
            }
            #pragma unroll
            for (int f = 0; f < 4; f++) {
                __half2 h0 = __floats2half2_rn(s[mt][2*f][0],   s[mt][2*f][1]);
                __half2 h1 = __floats2half2_rn(s[mt][2*f][2],   s[mt][2*f][3]);
                __half2 h2 = __floats2half2_rn(s[mt][2*f+1][0], s[mt][2*f+1][1]);
                __half2 h3 = __floats2half2_rn(s[mt][2*f+1][2], s[mt][2*f+1][3]);
                pf[mt][f][0] = *(uint32_t*)&h0;
                pf[mt][f][1] = *(uint32_t*)&h1;
                pf[mt][f][2] = *(uint32_t*)&h2;
                pf[mt][f][3] = *(uint32_t*)&h3;
            }
        }

        // O += P @ V_tile
        #pragma unroll
        for (int f = 0; f < 4; f++) {
            uint32_t vb[8][2];
            #pragma unroll
            for (int nt = 0; nt < 8; nt++) {
                const __half* vp = Vs + (nt*8 + gid)*VSTR + t*64 + f*16 + 2*tig;
                vb[nt][0] = *(const uint32_t*)(vp);
                vb[nt][1] = *(const uint32_t*)(vp + 8);
            }
            #pragma unroll
            for (int mt = 0; mt < 2; mt++)
                #pragma unroll
                for (int nt = 0; nt < 8; nt++)
                    mma16816(o[mt][nt], pf[mt][f], vb[nt]);
        }
    }

    // normalize + store
    #pragma unroll
    for (int mt = 0; mt < 2; mt++) {
        float invA = 1.f / lrow[mt][0];
        float invB = 1.f / lrow[mt][1];
        int rA = rowbase + mt*16 + gid;
        int rB = rA + 8;
        __half* oA = out + ((size_t)b*TT + rA)*CC + hh*DD;
        __half* oB = out + ((size_t)b*TT + rB)*CC + hh*DD;
        #pragma unroll
        for (int nt = 0; nt < 8; nt++) {
            __half2 hA = __floats2half2_rn(o[mt][nt][0]*invA, o[mt][nt][1]*invA);
            __half2 hB = __floats2half2_rn(o[mt][nt][2]*invB, o[mt][nt][3]*invB);
            *(__half2*)(oA + nt*8 + 2*tig) = hA;
            *(__half2*)(oB + nt*8 + 2*tig) = hB;
        }
    }
}

// ---------------- launch ----------------
extern "C" void kernel_launch(void* const* d_in, const int* in_sizes, int n_in,
                              void* d_out, int out_size)
{
    const float* x      = (const float*)d_in[0];
    const float* wq     = (const float*)d_in[1];
    const float* wk     = (const float*)d_in[2];
    const float* wv     = (const float*)d_in[3];
    const float* w_proj = (const float*)d_in[4];
    const float* b_proj = (const float*)d_in[5];
    const float* w1     = (const float*)d_in[6];
    const float* b1     = (const float*)d_in[7];
    const float* w2     = (const float*)d_in[8];
    const float* b2     = (const float*)d_in[9];
    const float* ln1_g  = (const float*)d_in[10];
    const float* ln1_b  = (const float*)d_in[11];
    const float* ln2_g  = (const float*)d_in[12];
    const float* ln2_b  = (const float*)d_in[13];
    float* out = (float*)d_out;

    void* p;
    cudaGetSymbolAddress(&p, g_h);      __half* h     = (__half*)p;
    cudaGetSymbolAddress(&p, g_q);      __half* q     = (__half*)p;
    cudaGetSymbolAddress(&p, g_k);      __half* k     = (__half*)p;
    cudaGetSymbolAddress(&p, g_vt);     __half* vt    = (__half*)p;
    cudaGetSymbolAddress(&p, g_attn);   __half* attn  = (__half*)p;
    cudaGetSymbolAddress(&p, g_hidden); __half* hid   = (__half*)p;
    cudaGetSymbolAddress(&p, g_w_qkv);  __half* wqkv  = (__half*)p;
    cudaGetSymbolAddress(&p, g_w_proj); __half* wprj  = (__half*)p;
    cudaGetSymbolAddress(&p, g_w1);     __half* ww1   = (__half*)p;
    cudaGetSymbolAddress(&p, g_w2);     __half* ww2   = (__half*)p;

    cudaFuncSetAttribute(attn_mma, cudaFuncAttributeMaxDynamicSharedMemorySize, ATTN_SMEM_B);
    cudaFuncSetAttribute(gemm_f16<0>, cudaFuncAttributeMaxDynamicSharedMemorySize, GEMM_SMEM_BYTES);
    cudaFuncSetAttribute(gemm_f16<1>, cudaFuncAttributeMaxDynamicSharedMemorySize, GEMM_SMEM_BYTES);
    cudaFuncSetAttribute(gemm_f16<2>, cudaFuncAttributeMaxDynamicSharedMemorySize, GEMM_SMEM_BYTES);
    cudaFuncSetAttribute(gemm_f16<3>, cudaFuncAttributeMaxDynamicSharedMemorySize, GEMM_SMEM_BYTES);

    // 0. weight pack
    pack_all<<<(P_TOT + 255)/256, 256>>>(wq, wk, wv, w_proj, w1, w2, wqkv, wprj, ww1, ww2);

    // 1. LN1 -> h
    ln_kernel<<<MM, 128>>>(x, ln1_g, ln1_b, h);

    // 2. fused QKV -> q, k (fp16 [b,h,t,d]), v transposed (fp16 [b,h,d,t])
    gemm_f16<0><<<dim3(NQKV/BN, MM/BM), 256, GEMM_SMEM_BYTES>>>(h, wqkv, nullptr, nullptr, nullptr, q, k, vt, CC, NQKV);

    // 3. tensor-core flash attention -> attn (fp16)
    attn_mma<<<dim3(2, HH, BB), 128, ATTN_SMEM_B>>>(q, k, vt, attn);

    // 4. proj + bias + residual(x) -> d_out
    gemm_f16<1><<<dim3(CC/BN, MM/BM), 256, GEMM_SMEM_BYTES>>>(attn, wprj, b_proj, x, out, nullptr, nullptr, nullptr, CC, CC);

    // 5. LN2 -> h
    ln_kernel<<<MM, 128>>>(out, ln2_g, ln2_b, h);

    // 6. fc1 + bias + relu -> hidden (fp16)
    gemm_f16<2><<<dim3(HID/BN, MM/BM), 256, GEMM_SMEM_BYTES>>>(h, ww1, b1, nullptr, nullptr, hid, nullptr, nullptr, CC, HID);

    // 7. fc2 + bias, accumulate into d_out
    gemm_f16<3><<<dim3(CC/BN, MM/BM), 256, GEMM_SMEM_BYTES>>>(hid, ww2, b2, nullptr, out, nullptr, nullptr, nullptr, HID, CC);
}

// round 9
// speedup vs baseline: 5.0166x; 1.0691x over previous
#include <cuda_runtime.h>
#include <cuda_fp16.h>
#include <cstdint>

#define BB   128
#define TT   256
#define CC   384
#define HH   6
#define DD   64
#define HID  1536
#define MM   (BB*TT)   // 32768
#define NQKV 1152

// GEMM tiling (fp16 operands, fp32 accum), 3-stage pipeline
#define BM 128
#define BN 128
#define BK 32
#define ASTR 40
#define A_BUF_H (BM*ASTR)
#define B_BUF_H (BN*ASTR)
#define STG_H   (A_BUF_H + B_BUF_H)
#define GEMM_SMEM_BYTES (3*STG_H*2)   // 61440 B

// attention smem strides (halves) — conflict-free
#define KSTR 72
#define VSTR 264
#define ATTN_SMEM_B ((TT*KSTR + DD*VSTR)*2)   // 70656

// ---------------- scratch ----------------
__device__ __half g_h[(size_t)MM*CC];
__device__ __half g_q[(size_t)BB*HH*TT*DD];
__device__ __half g_k[(size_t)BB*HH*TT*DD];
__device__ __half g_vt[(size_t)BB*HH*DD*TT];   // V transposed [b,h,d,t]
__device__ __half g_attn[(size_t)MM*CC];
__device__ __half g_hidden[(size_t)MM*HID];
__device__ __half g_w_qkv[(size_t)NQKV*CC];
__device__ __half g_w_proj[(size_t)CC*CC];
__device__ __half g_w1[(size_t)HID*CC];
__device__ __half g_w2[(size_t)CC*HID];

// ---------------- helpers ----------------
__device__ __forceinline__ void cp_async16(uint32_t s, const void* g) {
    asm volatile("cp.async.cg.shared.global [%0], [%1], 16;\n" :: "r"(s), "l"(g));
}
__device__ __forceinline__ void cp_commit() {
    asm volatile("cp.async.commit_group;\n");
}
template<int N> __device__ __forceinline__ void cp_wait() {
    asm volatile("cp.async.wait_group %0;\n" :: "n"(N));
}
__device__ __forceinline__ void mma16816(float* c, const uint32_t* a, const uint32_t* b) {
    asm volatile(
        "mma.sync.aligned.m16n8k16.row.col.f32.f16.f16.f32 "
        "{%0,%1,%2,%3}, {%4,%5,%6,%7}, {%8,%9}, {%0,%1,%2,%3};"
        : "+f"(c[0]), "+f"(c[1]), "+f"(c[2]), "+f"(c[3])
        : "r"(a[0]), "r"(a[1]), "r"(a[2]), "r"(a[3]), "r"(b[0]), "r"(b[1]));
}
__device__ __forceinline__ void ldsm_x4(uint32_t* r, uint32_t addr) {
    asm volatile("ldmatrix.sync.aligned.m8n8.x4.shared.b16 {%0,%1,%2,%3}, [%4];"
        : "=r"(r[0]), "=r"(r[1]), "=r"(r[2]), "=r"(r[3]) : "r"(addr));
}

// ---------------- fused weight pack ----------------
#define P_QKV  (CC*NQKV)
#define P_PRJ  (CC*CC)
#define P_W1   (CC*HID)
#define P_W2   (HID*CC)
#define P_TOT  (P_QKV + P_PRJ + P_W1 + P_W2)

__global__ void pack_all(const float* __restrict__ wq, const float* __restrict__ wk,
                         const float* __restrict__ wv, const float* __restrict__ wp,
                         const float* __restrict__ w1, const float* __restrict__ w2,
                         __half* __restrict__ oqkv, __half* __restrict__ oprj,
                         __half* __restrict__ ow1, __half* __restrict__ ow2)
{
    int idx = blockIdx.x * blockDim.x + threadIdx.x;
    if (idx >= P_TOT) return;
    if (idx < P_QKV) {
        int n = idx / CC, k = idx % CC;
        int src = n / CC, within = n % CC;
        int h = within >> 6, d = within & 63;
        const float* w = (src == 0) ? wq : (src == 1) ? wk : wv;
        oqkv[idx] = __float2half(w[((size_t)h*CC + k)*DD + d]);
    } else if (idx < P_QKV + P_PRJ) {
        int i = idx - P_QKV;
        int n = i / CC, k = i % CC;
        oprj[i] = __float2half(wp[(size_t)k*CC + n]);
    } else if (idx < P_QKV + P_PRJ + P_W1) {
        int i = idx - P_QKV - P_PRJ;
        int n = i / CC, k = i % CC;
        ow1[i] = __float2half(w1[(size_t)k*HID + n]);
    } else {
        int i = idx - P_QKV - P_PRJ - P_W1;
        int n = i / HID, k = i % HID;
        ow2[i] = __float2half(w2[(size_t)k*CC + n]);
    }
}

// ---------------- layernorm (fp16 output) ----------------
__global__ void ln_kernel(const float* __restrict__ x, const float* __restrict__ g,
                          const float* __restrict__ b, __half* __restrict__ out)
{
    int row = blockIdx.x;
    const float* xr = x + (size_t)row*CC;
    int t = threadIdx.x;
    float v0 = xr[t], v1 = xr[t+128], v2 = xr[t+256];
    float s  = v0+v1+v2;
    float ss = v0*v0 + v1*v1 + v2*v2;
    #pragma unroll
    for (int o = 16; o > 0; o >>= 1) {
        s  += __shfl_xor_sync(0xffffffffu, s,  o);
        ss += __shfl_xor_sync(0xffffffffu, ss, o);
    }
    __shared__ float sh_s[4], sh_ss[4];
    int w = t >> 5, lane = t & 31;
    if (lane == 0) { sh_s[w] = s; sh_ss[w] = ss; }
    __syncthreads();
    s  = sh_s[0]  + sh_s[1]  + sh_s[2]  + sh_s[3];
    ss = sh_ss[0] + sh_ss[1] + sh_ss[2] + sh_ss[3];
    float mean = s * (1.f/CC);
    float var  = ss * (1.f/CC) - mean*mean;
    float rstd = rsqrtf(var + 1e-5f);
    __half* orow = out + (size_t)row*CC;
    orow[t]     = __float2half((v0-mean)*rstd*g[t]     + b[t]);
    orow[t+128] = __float2half((v1-mean)*rstd*g[t+128] + b[t+128]);
    orow[t+256] = __float2half((v2-mean)*rstd*g[t+256] + b[t+256]);
}

// ---------------- fp16 tensor-core GEMM (ldmatrix + 3-stage cp.async) ----------------
// EPI: 0=QKV split; 1=proj(+bias+res)->f32; 2=fc1(relu)->fp16; 3=fc2(+bias,acc)->f32
template<int EPI>
__global__ __launch_bounds__(256, 2)
void gemm_f16(const __half* __restrict__ A, const __half* __restrict__ Bw,
              const float* __restrict__ bias, const float* __restrict__ res,
              float* __restrict__ outf, __half* __restrict__ outh,
              __half* __restrict__ out_k, __half* __restrict__ out_v,
              int K, int N)
{
    extern __shared__ __half smh[];
    uint32_t smem_u32 = (uint32_t)__cvta_generic_to_shared(smh);

    const int tid  = threadIdx.x;
    const int bm   = blockIdx.y * BM;
    const int bn   = blockIdx.x * BN;
    const int warp = tid >> 5, lane = tid & 31;
    const int wm   = (warp >> 1) * 32;
    const int wn   = (warp & 1)  * 64;
    const int gid  = lane >> 2, tig = lane & 3;

    // ldmatrix lane-address components
    const int aRow = wm + (lane & 15);              // + mt*16
    const int aK   = (lane >> 4) << 3;              // 0 or 8
    const int bRow = wn + (lane & 7) + ((lane & 16) ? 8 : 0);   // + p*16
    const int bK   = (lane & 8);                    // 0 or 8

    float acc[2][8][4];
    #pragma unroll
    for (int mt = 0; mt < 2; mt++)
        #pragma unroll
        for (int nt = 0; nt < 8; nt++)
            #pragma unroll
            for (int r = 0; r < 4; r++) acc[mt][nt][r] = 0.f;

    auto load_tile = [&](int k0, int buf) {
        #pragma unroll
        for (int i = 0; i < 2; i++) {
            int c = tid + i*256;
            int row = c >> 2, co = (c & 3) * 8;
            uint32_t s = smem_u32 + (uint32_t)(buf*STG_H + row*ASTR + co)*2u;
            cp_async16(s, A + (size_t)(bm + row)*K + k0 + co);
        }
        #pragma unroll
        for (int i = 0; i < 2; i++) {
            int c = tid + i*256;
            int row = c >> 2, co = (c & 3) * 8;
            uint32_t s = smem_u32 + (uint32_t)(buf*STG_H + A_BUF_H + row*ASTR + co)*2u;
            cp_async16(s, Bw + (size_t)(bn + row)*K + k0 + co);
        }
        cp_commit();
    };

    const int ntiles = K / BK;
    load_tile(0, 0);
    if (ntiles > 1) load_tile(BK, 1);

    for (int kt = 0; kt < ntiles; kt++) {
        if (kt + 1 < ntiles) cp_wait<1>(); else cp_wait<0>();
        __syncthreads();
        int cur = kt % 3;
        if (kt + 2 < ntiles) load_tile((kt+2)*BK, (kt+2) % 3);

        const uint32_t aBase = smem_u32 + (uint32_t)(cur*STG_H + aRow*ASTR + aK)*2u;
        const uint32_t bBase = smem_u32 + (uint32_t)(cur*STG_H + A_BUF_H + bRow*ASTR + bK)*2u;

        #pragma unroll
        for (int ks = 0; ks < 2; ks++) {
            const int k0 = ks * 16;
            uint32_t a[2][4];
            #pragma unroll
            for (int mt = 0; mt < 2; mt++)
                ldsm_x4(a[mt], aBase + (uint32_t)(mt*16*ASTR + k0)*2u);
            uint32_t b[8][2];
            #pragma unroll
            for (int p = 0; p < 4; p++) {
                uint32_t r[4];
                ldsm_x4(r, bBase + (uint32_t)(p*16*ASTR + k0)*2u);
                b[2*p][0]   = r[0];
                b[2*p][1]   = r[1];
                b[2*p+1][0] = r[2];
                b[2*p+1][1] = r[3];
            }
            #pragma unroll
            for (int mt = 0; mt < 2; mt++)
                #pragma unroll
                for (int nt = 0; nt < 8; nt++)
                    mma16816(acc[mt][nt], a[mt], b[nt]);
        }
    }

    // epilogue: c0=(gid,2tig) c1=(gid,2tig+1) c2=(gid+8,2tig) c3=(gid+8,2tig+1)
    #pragma unroll
    for (int mt = 0; mt < 2; mt++) {
        #pragma unroll
        for (int nt = 0; nt < 8; nt++) {
            #pragma unroll
            for (int r = 0; r < 4; r++) {
                int row = bm + wm + mt*16 + gid + ((r >= 2) ? 8 : 0);
                int col = bn + wn + nt*8 + tig*2 + (r & 1);
                float v = acc[mt][nt][r];
                if (EPI == 0) {
                    int src = col / CC, within = col % CC;
                    int h = within >> 6, d = within & 63;
                    int bidx = row / TT, t = row % TT;
                    if (src == 0)
                        outh[(((size_t)bidx*HH + h)*TT + t)*DD + d] = __float2half(v);
                    else if (src == 1)
                        out_k[(((size_t)bidx*HH + h)*TT + t)*DD + d] = __float2half(v);
                    else
                        out_v[(((size_t)bidx*HH + h)*DD + d)*TT + t] = __float2half(v);
                } else if (EPI == 1) {
                    outf[(size_t)row*N + col] = v + bias[col] + res[(size_t)row*N + col];
                } else if (EPI == 2) {
                    outh[(size_t)row*N + col] = __float2half(fmaxf(v + bias[col], 0.f));
                } else {
                    outf[(size_t)row*N + col] += v + bias[col];
                }
            }
        }
    }
}

// ---------------- tensor-core flash attention ----------------
__global__ __launch_bounds__(128, 2)
void attn_mma(const __half* __restrict__ q, const __half* __restrict__ k,
              const __half* __restrict__ vt, __half* __restrict__ out)
{
    extern __shared__ __half sm[];
    __half* Ks = sm;                 // [TT][KSTR]
    __half* Vs = sm + TT*KSTR;       // [DD][VSTR]
    uint32_t smemK = (uint32_t)__cvta_generic_to_shared(Ks);
    uint32_t smemV = (uint32_t)__cvta_generic_to_shared(Vs);

    const int half_ = blockIdx.x, hh = blockIdx.y, b = blockIdx.z;
    const int bh = b*HH + hh;
    const int tid = threadIdx.x, warp = tid >> 5, lane = tid & 31;
    const int gid = lane >> 2, tig = lane & 3;
    const int ntok = (half_ + 1) * 128;

    const __half* kg = k + (size_t)bh*TT*DD;
    for (int c = tid; c < ntok*8; c += 128) {
        int row = c >> 3, co = (c & 7)*8;
        cp_async16(smemK + (uint32_t)(row*KSTR + co)*2u, kg + row*DD + co);
    }
    const __half* vg = vt + (size_t)bh*DD*TT;
    const int vch = ntok >> 3;
    for (int c = tid; c < DD*vch; c += 128) {
        int d = c / vch, co = (c % vch)*8;
        cp_async16(smemV + (uint32_t)(d*VSTR + co)*2u, vg + d*TT + co);
    }
    cp_commit();

    const int rowbase = half_*128 + warp*32;
    const __half* qg = q + ((size_t)bh*TT + rowbase)*DD;
    uint32_t qf[2][4][4];
    #pragma unroll
    for (int mt = 0; mt < 2; mt++)
        #pragma unroll
        for (int f = 0; f < 4; f++) {
            const __half* p0 = qg + (mt*16 + gid)*DD + f*16 + 2*tig;
            qf[mt][f][0] = *(const uint32_t*)(p0);
            qf[mt][f][1] = *(const uint32_t*)(p0 + 8*DD);
            qf[mt][f][2] = *(const uint32_t*)(p0 + 8);
            qf[mt][f][3] = *(const uint32_t*)(p0 + 8*DD + 8);
        }

    float o[2][8][4];
    #pragma unroll
    for (int mt = 0; mt < 2; mt++)
        #pragma unroll
        for (int nt = 0; nt < 8; nt++)
            #pragma unroll
            for (int r = 0; r < 4; r++) o[mt][nt][r] = 0.f;
    float mrow[2][2] = {{-1e30f,-1e30f},{-1e30f,-1e30f}};
    float lrow[2][2] = {{0.f,0.f},{0.f,0.f}};
    const float scale = rsqrtf((float)CC);

    cp_wait<0>();
    __syncthreads();

    const int ntiles = (rowbase + 32 + 63) >> 6;
    for (int t = 0; t < ntiles; t++) {
        float s[2][8][4];
        #pragma unroll
        for (int mt = 0; mt < 2; mt++)
            #pragma unroll
            for (int nt = 0; nt < 8; nt++)
                #pragma unroll
                for (int r = 0; r < 4; r++) s[mt][nt][r] = 0.f;

        #pragma unroll
        for (int f = 0; f < 4; f++) {
            uint32_t bf[8][2];
            #pragma unroll
            for (int nt = 0; nt < 8; nt++) {
                const __half* bp = Ks + (t*64 + nt*8 + gid)*KSTR + f*16 + 2*tig;
                bf[nt][0] = *(const uint32_t*)(bp);
                bf[nt][1] = *(const uint32_t*)(bp + 8);
            }
            #pragma unroll
            for (int mt = 0; mt < 2; mt++)
                #pragma unroll
                for (int nt = 0; nt < 8; nt++)
                    mma16816(s[mt][nt], qf[mt][f], bf[nt]);
        }

        uint32_t pf[2][4][4];
        #pragma unroll
        for (int mt = 0; mt < 2; mt++) {
            const int rA = rowbase + mt*16 + gid;
            const int rB = rA + 8;
            #pragma unroll
            for (int nt = 0; nt < 8; nt++) {
                int c0 = t*64 + nt*8 + 2*tig;
                if (c0     > rA) s[mt][nt][0] = -1e30f;
                if (c0 + 1 > rA) s[mt][nt][1] = -1e30f;
                if (c0     > rB) s[mt][nt][2] = -1e30f;
                if (c0 + 1 > rB) s[mt][nt][3] = -1e30f;
            }
            float mxA = -1e30f, mxB = -1e30f;
            #pragma unroll
            for (int nt = 0; nt < 8; nt++) {
                mxA = fmaxf(mxA, fmaxf(s[mt][nt][0], s[mt][nt][1]));
                mxB = fmaxf(mxB, fmaxf(s[mt][nt][2], s[mt][nt][3]));
            }
            mxA = fmaxf(mxA, __shfl_xor_sync(0xffffffffu, mxA, 1));
            mxA = fmaxf(mxA, __shfl_xor_sync(0xffffffffu, mxA, 2));
            mxB = fmaxf(mxB, __shfl_xor_sync(0xffffffffu, mxB, 1));
            mxB = fmaxf(mxB, __shfl_xor_sync(0xffffffffu, mxB, 2));

            float mnA = fmaxf(mrow[mt][0], mxA);
            float mnB = fmaxf(mrow[mt][1], mxB);
            float cA  = __expf(scale*(mrow[mt][0] - mnA));
            float cB  = __expf(scale*(mrow[mt][1] - mnB));
            mrow[mt][0] = mnA; mrow[mt][1] = mnB;

            float sA = 0.f, sB = 0.f;
            #pragma unroll
            for (int nt = 0; nt < 8; nt++) {
                s[mt][nt][0] = __expf(scale*(s[mt][nt][0] - mnA));
                s[mt][nt][1] = __expf(scale*(s[mt][nt][1] - mnA));
                s[mt][nt][2] = __expf(scale*(s[mt][nt][2] - mnB));
                s[mt][nt][3] = __expf(scale*(s[mt][nt][3] - mnB));
                sA += s[mt][nt][0] + s[mt][nt][1];
                sB += s[mt][nt][2] + s[mt][nt][3];
            }
            sA += __shfl_xor_sync(0xffffffffu, sA, 1);
            sA += __shfl_xor_sync(0xffffffffu, sA, 2);
            sB += __shfl_xor_sync(0xffffffffu, sB, 1);
            sB += __shfl_xor_sync(0xffffffffu, sB, 2);
            lrow[mt][0] = lrow[mt][0]*cA + sA;
            lrow[mt][1] = lrow[mt][1]*cB + sB;

            #pragma unroll
            for (int nt = 0; nt < 8; nt++) {
                o[mt][nt][0] *= cA; o[mt][nt][1] *= cA;
                o[mt][nt][2] *= cB; o[mt][nt][3] *= cB;
            }
            #pragma unroll
            for (int f = 0; f < 4; f++) {
                __half2 h0 = __floats2half2_rn(s[mt][2*f][0],   s[mt][2*f][1]);
                __half2 h1 = __floats2half2_rn(s[mt][2*f][2],   s[mt][2*f][3]);
                __half2 h2 = __floats2half2_rn(s[mt][2*f+1][0], s[mt][2*f+1][1]);
                __half2 h3 = __floats2half2_rn(s[mt][2*f+1][2], s[mt][2*f+1][3]);
                pf[mt][f][0] = *(uint32_t*)&h0;
                pf[mt][f][1] = *(uint32_t*)&h1;
                pf[mt][f][2] = *(uint32_t*)&h2;
                pf[mt][f][3] = *(uint32_t*)&h3;
            }
        }

        #pragma unroll
        for (int f = 0; f < 4; f++) {
            uint32_t vb[8][2];
            #pragma unroll
            for (int nt = 0; nt < 8; nt++) {
                const __half* vp = Vs + (nt*8 + gid)*VSTR + t*64 + f*16 + 2*tig;
                vb[nt][0] = *(const uint32_t*)(vp);
                vb[nt][1] = *(const uint32_t*)(vp + 8);
            }
            #pragma unroll
            for (int mt = 0; mt < 2; mt++)
                #pragma unroll
                for (int nt = 0; nt < 8; nt++)
                    mma16816(o[mt][nt], pf[mt][f], vb[nt]);
        }
    }

    #pragma unroll
    for (int mt = 0; mt < 2; mt++) {
        float invA = 1.f / lrow[mt][0];
        float invB = 1.f / lrow[mt][1];
        int rA = rowbase + mt*16 + gid;
        int rB = rA + 8;
        __half* oA = out + ((size_t)b*TT + rA)*CC + hh*DD;
        __half* oB = out + ((size_t)b*TT + rB)*CC + hh*DD;
        #pragma unroll
        for (int nt = 0; nt < 8; nt++) {
            __half2 hA = __floats2half2_rn(o[mt][nt][0]*invA, o[mt][nt][1]*invA);
            __half2 hB = __floats2half2_rn(o[mt][nt][2]*invB, o[mt][nt][3]*invB);
            *(__half2*)(oA + nt*8 + 2*tig) = hA;
            *(__half2*)(oB + nt*8 + 2*tig) = hB;
        }
    }
}

// ---------------- launch ----------------
extern "C" void kernel_launch(void* const* d_in, const int* in_sizes, int n_in,
                              void* d_out, int out_size)
{
    const float* x      = (const float*)d_in[0];
    const float* wq     = (const float*)d_in[1];
    const float* wk     = (const float*)d_in[2];
    const float* wv     = (const float*)d_in[3];
    const float* w_proj = (const float*)d_in[4];
    const float* b_proj = (const float*)d_in[5];
    const float* w1     = (const float*)d_in[6];
    const float* b1     = (const float*)d_in[7];
    const float* w2     = (const float*)d_in[8];
    const float* b2     = (const float*)d_in[9];
    const float* ln1_g  = (const float*)d_in[10];
    const float* ln1_b  = (const float*)d_in[11];
    const float* ln2_g  = (const float*)d_in[12];
    const float* ln2_b  = (const float*)d_in[13];
    float* out = (float*)d_out;

    void* p;
    cudaGetSymbolAddress(&p, g_h);      __half* h     = (__half*)p;
    cudaGetSymbolAddress(&p, g_q);      __half* q     = (__half*)p;
    cudaGetSymbolAddress(&p, g_k);      __half* k     = (__half*)p;
    cudaGetSymbolAddress(&p, g_vt);     __half* vt    = (__half*)p;
    cudaGetSymbolAddress(&p, g_attn);   __half* attn  = (__half*)p;
    cudaGetSymbolAddress(&p, g_hidden); __half* hid   = (__half*)p;
    cudaGetSymbolAddress(&p, g_w_qkv);  __half* wqkv  = (__half*)p;
    cudaGetSymbolAddress(&p, g_w_proj); __half* wprj  = (__half*)p;
    cudaGetSymbolAddress(&p, g_w1);     __half* ww1   = (__half*)p;
    cudaGetSymbolAddress(&p, g_w2);     __half* ww2   = (__half*)p;

    cudaFuncSetAttribute(attn_mma, cudaFuncAttributeMaxDynamicSharedMemorySize, ATTN_SMEM_B);
    cudaFuncSetAttribute(gemm_f16<0>, cudaFuncAttributeMaxDynamicSharedMemorySize, GEMM_SMEM_BYTES);
    cudaFuncSetAttribute(gemm_f16<1>, cudaFuncAttributeMaxDynamicSharedMemorySize, GEMM_SMEM_BYTES);
    cudaFuncSetAttribute(gemm_f16<2>, cudaFuncAttributeMaxDynamicSharedMemorySize, GEMM_SMEM_BYTES);
    cudaFuncSetAttribute(gemm_f16<3>, cudaFuncAttributeMaxDynamicSharedMemorySize, GEMM_SMEM_BYTES);

    // 0. weight pack
    pack_all<<<(P_TOT + 255)/256, 256>>>(wq, wk, wv, w_proj, w1, w2, wqkv, wprj, ww1, ww2);

    // 1. LN1 -> h
    ln_kernel<<<MM, 128>>>(x, ln1_g, ln1_b, h);

    // 2. fused QKV -> q, k (fp16 [b,h,t,d]), v transposed (fp16 [b,h,d,t])
    gemm_f16<0><<<dim3(NQKV/BN, MM/BM), 256, GEMM_SMEM_BYTES>>>(h, wqkv, nullptr, nullptr, nullptr, q, k, vt, CC, NQKV);

    // 3. tensor-core flash attention -> attn (fp16)
    attn_mma<<<dim3(2, HH, BB), 128, ATTN_SMEM_B>>>(q, k, vt, attn);

    // 4. proj + bias + residual(x) -> d_out
    gemm_f16<1><<<dim3(CC/BN, MM/BM), 256, GEMM_SMEM_BYTES>>>(attn, wprj, b_proj, x, out, nullptr, nullptr, nullptr, CC, CC);

    // 5. LN2 -> h
    ln_kernel<<<MM, 128>>>(out, ln2_g, ln2_b, h);

    // 6. fc1 + bias + relu -> hidden (fp16)
    gemm_f16<2><<<dim3(HID/BN, MM/BM), 256, GEMM_SMEM_BYTES>>>(h, ww1, b1, nullptr, nullptr, hid, nullptr, nullptr, CC, HID);

    // 7. fc2 + bias, accumulate into d_out
    gemm_f16<3><<<dim3(CC/BN, MM/BM), 256, GEMM_SMEM_BYTES>>>(hid, ww2, b2, nullptr, out, nullptr, nullptr, nullptr, HID, CC);
}

// round 10
// speedup vs baseline: 5.3320x; 1.0629x over previous
#include <cuda_runtime.h>
#include <cuda_fp16.h>
#include <cstdint>

#define BB   128
#define TT   256
#define CC   384
#define HH   6
#define DD   64
#define HID  1536
#define MM   (BB*TT)   // 32768
#define NQKV 1152

// GEMM tiling: CTA 256x128, 8 warps (4x2), warp tile 64x64, BK=32, 3-stage
#define BM 256
#define BN 128
#define BK 32
#define ASTR 40
#define A_BUF_H (BM*ASTR)             // 10240 halves
#define B_BUF_H (BN*ASTR)             // 5120 halves
#define STG_H   (A_BUF_H + B_BUF_H)   // 15360 halves per stage
#define GEMM_SMEM_BYTES (3*STG_H*2)   // 92160 B

// attention smem strides (halves) — conflict-free
#define KSTR 72
#define VSTR 264
#define ATTN_SMEM_B ((TT*KSTR + DD*VSTR)*2)   // 70656

// ---------------- scratch ----------------
__device__ __half g_h[(size_t)MM*CC];
__device__ __half g_q[(size_t)BB*HH*TT*DD];
__device__ __half g_k[(size_t)BB*HH*TT*DD];
__device__ __half g_vt[(size_t)BB*HH*DD*TT];   // V transposed [b,h,d,t]
__device__ __half g_attn[(size_t)MM*CC];
__device__ __half g_hidden[(size_t)MM*HID];
__device__ __half g_w_qkv[(size_t)NQKV*CC];
__device__ __half g_w_proj[(size_t)CC*CC];
__device__ __half g_w1[(size_t)HID*CC];
__device__ __half g_w2[(size_t)CC*HID];

// ---------------- helpers ----------------
__device__ __forceinline__ void cp_async16(uint32_t s, const void* g) {
    asm volatile("cp.async.cg.shared.global [%0], [%1], 16;\n" :: "r"(s), "l"(g));
}
__device__ __forceinline__ void cp_commit() {
    asm volatile("cp.async.commit_group;\n");
}
template<int N> __device__ __forceinline__ void cp_wait() {
    asm volatile("cp.async.wait_group %0;\n" :: "n"(N));
}
__device__ __forceinline__ void mma16816(float* c, const uint32_t* a, const uint32_t* b) {
    asm volatile(
        "mma.sync.aligned.m16n8k16.row.col.f32.f16.f16.f32 "
        "{%0,%1,%2,%3}, {%4,%5,%6,%7}, {%8,%9}, {%0,%1,%2,%3};"
        : "+f"(c[0]), "+f"(c[1]), "+f"(c[2]), "+f"(c[3])
        : "r"(a[0]), "r"(a[1]), "r"(a[2]), "r"(a[3]), "r"(b[0]), "r"(b[1]));
}
__device__ __forceinline__ void ldsm_x4(uint32_t* r, uint32_t addr) {
    asm volatile("ldmatrix.sync.aligned.m8n8.x4.shared.b16 {%0,%1,%2,%3}, [%4];"
        : "=r"(r[0]), "=r"(r[1]), "=r"(r[2]), "=r"(r[3]) : "r"(addr));
}

// ---------------- fused weight pack ----------------
#define P_QKV  (CC*NQKV)
#define P_PRJ  (CC*CC)
#define P_W1   (CC*HID)
#define P_W2   (HID*CC)
#define P_TOT  (P_QKV + P_PRJ + P_W1 + P_W2)

__global__ void pack_all(const float* __restrict__ wq, const float* __restrict__ wk,
                         const float* __restrict__ wv, const float* __restrict__ wp,
                         const float* __restrict__ w1, const float* __restrict__ w2,
                         __half* __restrict__ oqkv, __half* __restrict__ oprj,
                         __half* __restrict__ ow1, __half* __restrict__ ow2)
{
    int idx = blockIdx.x * blockDim.x + threadIdx.x;
    if (idx >= P_TOT) return;
    if (idx < P_QKV) {
        int n = idx / CC, k = idx % CC;
        int src = n / CC, within = n % CC;
        int h = within >> 6, d = within & 63;
        const float* w = (src == 0) ? wq : (src == 1) ? wk : wv;
        oqkv[idx] = __float2half(w[((size_t)h*CC + k)*DD + d]);
    } else if (idx < P_QKV + P_PRJ) {
        int i = idx - P_QKV;
        int n = i / CC, k = i % CC;
        oprj[i] = __float2half(wp[(size_t)k*CC + n]);
    } else if (idx < P_QKV + P_PRJ + P_W1) {
        int i = idx - P_QKV - P_PRJ;
        int n = i / CC, k = i % CC;
        ow1[i] = __float2half(w1[(size_t)k*HID + n]);
    } else {
        int i = idx - P_QKV - P_PRJ - P_W1;
        int n = i / HID, k = i % HID;
        ow2[i] = __float2half(w2[(size_t)k*CC + n]);
    }
}

// ---------------- layernorm (fp16 output) ----------------
__global__ void ln_kernel(const float* __restrict__ x, const float* __restrict__ g,
                          const float* __restrict__ b, __half* __restrict__ out)
{
    int row = blockIdx.x;
    const float* xr = x + (size_t)row*CC;
    int t = threadIdx.x;
    float v0 = xr[t], v1 = xr[t+128], v2 = xr[t+256];
    float s  = v0+v1+v2;
    float ss = v0*v0 + v1*v1 + v2*v2;
    #pragma unroll
    for (int o = 16; o > 0; o >>= 1) {
        s  += __shfl_xor_sync(0xffffffffu, s,  o);
        ss += __shfl_xor_sync(0xffffffffu, ss, o);
    }
    __shared__ float sh_s[4], sh_ss[4];
    int w = t >> 5, lane = t & 31;
    if (lane == 0) { sh_s[w] = s; sh_ss[w] = ss; }
    __syncthreads();
    s  = sh_s[0]  + sh_s[1]  + sh_s[2]  + sh_s[3];
    ss = sh_ss[0] + sh_ss[1] + sh_ss[2] + sh_ss[3];
    float mean = s * (1.f/CC);
    float var  = ss * (1.f/CC) - mean*mean;
    float rstd = rsqrtf(var + 1e-5f);
    __half* orow = out + (size_t)row*CC;
    orow[t]     = __float2half((v0-mean)*rstd*g[t]     + b[t]);
    orow[t+128] = __float2half((v1-mean)*rstd*g[t+128] + b[t+128]);
    orow[t+256] = __float2half((v2-mean)*rstd*g[t+256] + b[t+256]);
}

// ---------------- fp16 tensor-core GEMM (64x64 warp tile) ----------------
// EPI: 0=QKV split; 1=proj(+bias+res)->f32; 2=fc1(relu)->fp16; 3=fc2(+bias,acc)->f32
template<int EPI>
__global__ __launch_bounds__(256, 1)
void gemm_f16(const __half* __restrict__ A, const __half* __restrict__ Bw,
              const float* __restrict__ bias, const float* __restrict__ res,
              float* __restrict__ outf, __half* __restrict__ outh,
              __half* __restrict__ out_k, __half* __restrict__ out_v,
              int K, int N)
{
    extern __shared__ __half smh[];
    uint32_t smem_u32 = (uint32_t)__cvta_generic_to_shared(smh);

    const int tid  = threadIdx.x;
    const int bm   = blockIdx.y * BM;
    const int bn   = blockIdx.x * BN;
    const int warp = tid >> 5, lane = tid & 31;
    const int wm   = (warp >> 1) * 64;    // 4 warp rows
    const int wn   = (warp & 1)  * 64;    // 2 warp cols
    const int gid  = lane >> 2, tig = lane & 3;

    // ldmatrix lane-address components
    const int aRow = wm + (lane & 15);              // + mt*16
    const int aK   = (lane >> 4) << 3;              // 0 or 8
    const int bRow = wn + (lane & 7) + ((lane & 16) ? 8 : 0);   // + p*16
    const int bK   = (lane & 8);                    // 0 or 8

    float acc[4][8][4];
    #pragma unroll
    for (int mt = 0; mt < 4; mt++)
        #pragma unroll
        for (int nt = 0; nt < 8; nt++)
            #pragma unroll
            for (int r = 0; r < 4; r++) acc[mt][nt][r] = 0.f;

    // global loads: A 256x32 halves = 1024 x 16B (4/thread); B 128x32 = 512 (2/thread)
    auto load_tile = [&](int k0, int buf) {
        #pragma unroll
        for (int i = 0; i < 4; i++) {
            int c = tid + i*256;
            int row = c >> 2, co = (c & 3) * 8;
            uint32_t s = smem_u32 + (uint32_t)(buf*STG_H + row*ASTR + co)*2u;
            cp_async16(s, A + (size_t)(bm + row)*K + k0 + co);
        }
        #pragma unroll
        for (int i = 0; i < 2; i++) {
            int c = tid + i*256;
            int row = c >> 2, co = (c & 3) * 8;
            uint32_t s = smem_u32 + (uint32_t)(buf*STG_H + A_BUF_H + row*ASTR + co)*2u;
            cp_async16(s, Bw + (size_t)(bn + row)*K + k0 + co);
        }
        cp_commit();
    };

    const int ntiles = K / BK;
    load_tile(0, 0);
    if (ntiles > 1) load_tile(BK, 1);

    for (int kt = 0; kt < ntiles; kt++) {
        if (kt + 1 < ntiles) cp_wait<1>(); else cp_wait<0>();
        __syncthreads();
        int cur = kt % 3;
        if (kt + 2 < ntiles) load_tile((kt+2)*BK, (kt+2) % 3);

        const uint32_t aBase = smem_u32 + (uint32_t)(cur*STG_H + aRow*ASTR + aK)*2u;
        const uint32_t bBase = smem_u32 + (uint32_t)(cur*STG_H + A_BUF_H + bRow*ASTR + bK)*2u;

        #pragma unroll
        for (int ks = 0; ks < 2; ks++) {
            const int k0 = ks * 16;
            uint32_t a[4][4];
            #pragma unroll
            for (int mt = 0; mt < 4; mt++)
                ldsm_x4(a[mt], aBase + (uint32_t)(mt*16*ASTR + k0)*2u);
            uint32_t b[8][2];
            #pragma unroll
            for (int p = 0; p < 4; p++) {
                uint32_t r[4];
                ldsm_x4(r, bBase + (uint32_t)(p*16*ASTR + k0)*2u);
                b[2*p][0]   = r[0];
                b[2*p][1]   = r[1];
                b[2*p+1][0] = r[2];
                b[2*p+1][1] = r[3];
            }
            #pragma unroll
            for (int mt = 0; mt < 4; mt++)
                #pragma unroll
                for (int nt = 0; nt < 8; nt++)
                    mma16816(acc[mt][nt], a[mt], b[nt]);
        }
    }

    // epilogue — paired stores: (c0,c1) cols 2tig,2tig+1 row gid; (c2,c3) row gid+8
    #pragma unroll
    for (int mt = 0; mt < 4; mt++) {
        #pragma unroll
        for (int nt = 0; nt < 8; nt++) {
            int row0 = bm + wm + mt*16 + gid;
            int col  = bn + wn + nt*8 + tig*2;
            #pragma unroll
            for (int half2_idx = 0; half2_idx < 2; half2_idx++) {
                int row = row0 + half2_idx*8;
                float v0 = acc[mt][nt][half2_idx*2];
                float v1 = acc[mt][nt][half2_idx*2+1];
                if (EPI == 0) {
                    int src = col / CC, within = col % CC;
                    int h = within >> 6, d = within & 63;
                    int bidx = row / TT, t = row % TT;
                    if (src == 0)
                        *(__half2*)&outh[(((size_t)bidx*HH + h)*TT + t)*DD + d] = __floats2half2_rn(v0, v1);
                    else if (src == 1)
                        *(__half2*)&out_k[(((size_t)bidx*HH + h)*TT + t)*DD + d] = __floats2half2_rn(v0, v1);
                    else {
                        out_v[(((size_t)bidx*HH + h)*DD + d)*TT + t]     = __float2half(v0);
                        out_v[(((size_t)bidx*HH + h)*DD + d + 1)*TT + t] = __float2half(v1);
                    }
                } else if (EPI == 1) {
                    const float2 rv = *(const float2*)&res[(size_t)row*N + col];
                    float2 o;
                    o.x = v0 + bias[col]   + rv.x;
                    o.y = v1 + bias[col+1] + rv.y;
                    *(float2*)&outf[(size_t)row*N + col] = o;
                } else if (EPI == 2) {
                    *(__half2*)&outh[(size_t)row*N + col] =
                        __floats2half2_rn(fmaxf(v0 + bias[col], 0.f), fmaxf(v1 + bias[col+1], 0.f));
                } else {
                    float2 o = *(const float2*)&outf[(size_t)row*N + col];
                    o.x += v0 + bias[col];
                    o.y += v1 + bias[col+1];
                    *(float2*)&outf[(size_t)row*N + col] = o;
                }
            }
        }
    }
}

// ---------------- tensor-core flash attention (unchanged from r9) ----------------
__global__ __launch_bounds__(128, 2)
void attn_mma(const __half* __restrict__ q, const __half* __restrict__ k,
              const __half* __restrict__ vt, __half* __restrict__ out)
{
    extern __shared__ __half sm[];
    __half* Ks = sm;
    __half* Vs = sm + TT*KSTR;
    uint32_t smemK = (uint32_t)__cvta_generic_to_shared(Ks);
    uint32_t smemV = (uint32_t)__cvta_generic_to_shared(Vs);

    const int half_ = blockIdx.x, hh = blockIdx.y, b = blockIdx.z;
    const int bh = b*HH + hh;
    const int tid = threadIdx.x, warp = tid >> 5, lane = tid & 31;
    const int gid = lane >> 2, tig = lane & 3;
    const int ntok = (half_ + 1) * 128;

    const __half* kg = k + (size_t)bh*TT*DD;
    for (int c = tid; c < ntok*8; c += 128) {
        int row = c >> 3, co = (c & 7)*8;
        cp_async16(smemK + (uint32_t)(row*KSTR + co)*2u, kg + row*DD + co);
    }
    const __half* vg = vt + (size_t)bh*DD*TT;
    const int vch = ntok >> 3;
    for (int c = tid; c < DD*vch; c += 128) {
        int d = c / vch, co = (c % vch)*8;
        cp_async16(smemV + (uint32_t)(d*VSTR + co)*2u, vg + d*TT + co);
    }
    cp_commit();

    const int rowbase = half_*128 + warp*32;
    const __half* qg = q + ((size_t)bh*TT + rowbase)*DD;
    uint32_t qf[2][4][4];
    #pragma unroll
    for (int mt = 0; mt < 2; mt++)
        #pragma unroll
        for (int f = 0; f < 4; f++) {
            const __half* p0 = qg + (mt*16 + gid)*DD + f*16 + 2*tig;
            qf[mt][f][0] = *(const uint32_t*)(p0);
            qf[mt][f][1] = *(const uint32_t*)(p0 + 8*DD);
            qf[mt][f][2] = *(const uint32_t*)(p0 + 8);
            qf[mt][f][3] = *(const uint32_t*)(p0 + 8*DD + 8);
        }

    float o[2][8][4];
    #pragma unroll
    for (int mt = 0; mt < 2; mt++)
        #pragma unroll
        for (int nt = 0; nt < 8; nt++)
            #pragma unroll
            for (int r = 0; r < 4; r++) o[mt][nt][r] = 0.f;
    float mrow[2][2] = {{-1e30f,-1e30f},{-1e30f,-1e30f}};
    float lrow[2][2] = {{0.f,0.f},{0.f,0.f}};
    const float scale = rsqrtf((float)CC);

    cp_wait<0>();
    __syncthreads();

    const int ntiles = (rowbase + 32 + 63) >> 6;
    for (int t = 0; t < ntiles; t++) {
        float s[2][8][4];
        #pragma unroll
        for (int mt = 0; mt < 2; mt++)
            #pragma unroll
            for (int nt = 0; nt < 8; nt++)
                #pragma unroll
                for (int r = 0; r < 4; r++) s[mt][nt][r] = 0.f;

        #pragma unroll
        for (int f = 0; f < 4; f++) {
            uint32_t bf[8][2];
            #pragma unroll
            for (int nt = 0; nt < 8; nt++) {
                const __half* bp = Ks + (t*64 + nt*8 + gid)*KSTR + f*16 + 2*tig;
                bf[nt][0] = *(const uint32_t*)(bp);
                bf[nt][1] = *(const uint32_t*)(bp + 8);
            }
            #pragma unroll
            for (int mt = 0; mt < 2; mt++)
                #pragma unroll
                for (int nt = 0; nt < 8; nt++)
                    mma16816(s[mt][nt], qf[mt][f], bf[nt]);
        }

        uint32_t pf[2][4][4];
        #pragma unroll
        for (int mt = 0; mt < 2; mt++) {
            const int rA = rowbase + mt*16 + gid;
            const int rB = rA + 8;
            #pragma unroll
            for (int nt = 0; nt < 8; nt++) {
                int c0 = t*64 + nt*8 + 2*tig;
                if (c0     > rA) s[mt][nt][0] = -1e30f;
                if (c0 + 1 > rA) s[mt][nt][1] = -1e30f;
                if (c0     > rB) s[mt][nt][2] = -1e30f;
                if (c0 + 1 > rB) s[mt][nt][3] = -1e30f;
            }
            float mxA = -1e30f, mxB = -1e30f;
            #pragma unroll
            for (int nt = 0; nt < 8; nt++) {
                mxA = fmaxf(mxA, fmaxf(s[mt][nt][0], s[mt][nt][1]));
                mxB = fmaxf(mxB, fmaxf(s[mt][nt][2], s[mt][nt][3]));
            }
            mxA = fmaxf(mxA, __shfl_xor_sync(0xffffffffu, mxA, 1));
            mxA = fmaxf(mxA, __shfl_xor_sync(0xffffffffu, mxA, 2));
            mxB = fmaxf(mxB, __shfl_xor_sync(0xffffffffu, mxB, 1));
            mxB = fmaxf(mxB, __shfl_xor_sync(0xffffffffu, mxB, 2));

            float mnA = fmaxf(mrow[mt][0], mxA);
            float mnB = fmaxf(mrow[mt][1], mxB);
            float cA  = __expf(scale*(mrow[mt][0] - mnA));
            float cB  = __expf(scale*(mrow[mt][1] - mnB));
            mrow[mt][0] = mnA; mrow[mt][1] = mnB;

            float sA = 0.f, sB = 0.f;
            #pragma unroll
            for (int nt = 0; nt < 8; nt++) {
                s[mt][nt][0] = __expf(scale*(s[mt][nt][0] - mnA));
                s[mt][nt][1] = __expf(scale*(s[mt][nt][1] - mnA));
                s[mt][nt][2] = __expf(scale*(s[mt][nt][2] - mnB));
                s[mt][nt][3] = __expf(scale*(s[mt][nt][3] - mnB));
                sA += s[mt][nt][0] + s[mt][nt][1];
                sB += s[mt][nt][2] + s[mt][nt][3];
            }
            sA += __shfl_xor_sync(0xffffffffu, sA, 1);
            sA += __shfl_xor_sync(0xffffffffu, sA, 2);
            sB += __shfl_xor_sync(0xffffffffu, sB, 1);
            sB += __shfl_xor_sync(0xffffffffu, sB, 2);
            lrow[mt][0] = lrow[mt][0]*cA + sA;
            lrow[mt][1] = lrow[mt][1]*cB + sB;

            #pragma unroll
            for (int nt = 0; nt < 8; nt++) {
                o[mt][nt][0] *= cA; o[mt][nt][1] *= cA;
                o[mt][nt][2] *= cB; o[mt][nt][3] *= cB;
            }
            #pragma unroll
            for (int f = 0; f < 4; f++) {
                __half2 h0 = __floats2half2_rn(s[mt][2*f][0],   s[mt][2*f][1]);
                __half2 h1 = __floats2half2_rn(s[mt][2*f][2],   s[mt][2*f][3]);
                __half2 h2 = __floats2half2_rn(s[mt][2*f+1][0], s[mt][2*f+1][1]);
                __half2 h3 = __floats2half2_rn(s[mt][2*f+1][2], s[mt][2*f+1][3]);
                pf[mt][f][0] = *(uint32_t*)&h0;
                pf[mt][f][1] = *(uint32_t*)&h1;
                pf[mt][f][2] = *(uint32_t*)&h2;
                pf[mt][f][3] = *(uint32_t*)&h3;
            }
        }

        #pragma unroll
        for (int f = 0; f < 4; f++) {
            uint32_t vb[8][2];
            #pragma unroll
            for (int nt = 0; nt < 8; nt++) {
                const __half* vp = Vs + (nt*8 + gid)*VSTR + t*64 + f*16 + 2*tig;
                vb[nt][0] = *(const uint32_t*)(vp);
                vb[nt][1] = *(const uint32_t*)(vp + 8);
            }
            #pragma unroll
            for (int mt = 0; mt < 2; mt++)
                #pragma unroll
                for (int nt = 0; nt < 8; nt++)
                    mma16816(o[mt][nt], pf[mt][f], vb[nt]);
        }
    }

    #pragma unroll
    for (int mt = 0; mt < 2; mt++) {
        float invA = 1.f / lrow[mt][0];
        float invB = 1.f / lrow[mt][1];
        int rA = rowbase + mt*16 + gid;
        int rB = rA + 8;
        __half* oA = out + ((size_t)b*TT + rA)*CC + hh*DD;
        __half* oB = out + ((size_t)b*TT + rB)*CC + hh*DD;
        #pragma unroll
        for (int nt = 0; nt < 8; nt++) {
            __half2 hA = __floats2half2_rn(o[mt][nt][0]*invA, o[mt][nt][1]*invA);
            __half2 hB = __floats2half2_rn(o[mt][nt][2]*invB, o[mt][nt][3]*invB);
            *(__half2*)(oA + nt*8 + 2*tig) = hA;
            *(__half2*)(oB + nt*8 + 2*tig) = hB;
        }
    }
}

// ---------------- launch ----------------
extern "C" void kernel_launch(void* const* d_in, const int* in_sizes, int n_in,
                              void* d_out, int out_size)
{
    const float* x      = (const float*)d_in[0];
    const float* wq     = (const float*)d_in[1];
    const float* wk     = (const float*)d_in[2];
    const float* wv     = (const float*)d_in[3];
    const float* w_proj = (const float*)d_in[4];
    const float* b_proj = (const float*)d_in[5];
    const float* w1     = (const float*)d_in[6];
    const float* b1     = (const float*)d_in[7];
    const float* w2     = (const float*)d_in[8];
    const float* b2     = (const float*)d_in[9];
    const float* ln1_g  = (const float*)d_in[10];
    const float* ln1_b  = (const float*)d_in[11];
    const float* ln2_g  = (const float*)d_in[12];
    const float* ln2_b  = (const float*)d_in[13];
    float* out = (float*)d_out;

    void* p;
    cudaGetSymbolAddress(&p, g_h);      __half* h     = (__half*)p;
    cudaGetSymbolAddress(&p, g_q);      __half* q     = (__half*)p;
    cudaGetSymbolAddress(&p, g_k);      __half* k     = (__half*)p;
    cudaGetSymbolAddress(&p, g_vt);     __half* vt    = (__half*)p;
    cudaGetSymbolAddress(&p, g_attn);   __half* attn  = (__half*)p;
    cudaGetSymbolAddress(&p, g_hidden); __half* hid   = (__half*)p;
    cudaGetSymbolAddress(&p, g_w_qkv);  __half* wqkv  = (__half*)p;
    cudaGetSymbolAddress(&p, g_w_proj); __half* wprj  = (__half*)p;
    cudaGetSymbolAddress(&p, g_w1);     __half* ww1   = (__half*)p;
    cudaGetSymbolAddress(&p, g_w2);     __half* ww2   = (__half*)p;

    cudaFuncSetAttribute(attn_mma, cudaFuncAttributeMaxDynamicSharedMemorySize, ATTN_SMEM_B);
    cudaFuncSetAttribute(gemm_f16<0>, cudaFuncAttributeMaxDynamicSharedMemorySize, GEMM_SMEM_BYTES);
    cudaFuncSetAttribute(gemm_f16<1>, cudaFuncAttributeMaxDynamicSharedMemorySize, GEMM_SMEM_BYTES);
    cudaFuncSetAttribute(gemm_f16<2>, cudaFuncAttributeMaxDynamicSharedMemorySize, GEMM_SMEM_BYTES);
    cudaFuncSetAttribute(gemm_f16<3>, cudaFuncAttributeMaxDynamicSharedMemorySize, GEMM_SMEM_BYTES);

    // 0. weight pack
    pack_all<<<(P_TOT + 255)/256, 256>>>(wq, wk, wv, w_proj, w1, w2, wqkv, wprj, ww1, ww2);

    // 1. LN1 -> h
    ln_kernel<<<MM, 128>>>(x, ln1_g, ln1_b, h);

    // 2. fused QKV -> q, k (fp16 [b,h,t,d]), v transposed (fp16 [b,h,d,t])
    gemm_f16<0><<<dim3(NQKV/BN, MM/BM), 256, GEMM_SMEM_BYTES>>>(h, wqkv, nullptr, nullptr, nullptr, q, k, vt, CC, NQKV);

    // 3. tensor-core flash attention -> attn (fp16)
    attn_mma<<<dim3(2, HH, BB), 128, ATTN_SMEM_B>>>(q, k, vt, attn);

    // 4. proj + bias + residual(x) -> d_out
    gemm_f16<1><<<dim3(CC/BN, MM/BM), 256, GEMM_SMEM_BYTES>>>(attn, wprj, b_proj, x, out, nullptr, nullptr, nullptr, CC, CC);

    // 5. LN2 -> h
    ln_kernel<<<MM, 128>>>(out, ln2_g, ln2_b, h);

    // 6. fc1 + bias + relu -> hidden (fp16)
    gemm_f16<2><<<dim3(HID/BN, MM/BM), 256, GEMM_SMEM_BYTES>>>(h, ww1, b1, nullptr, nullptr, hid, nullptr, nullptr, CC, HID);

    // 7. fc2 + bias, accumulate into d_out
    gemm_f16<3><<<dim3(CC/BN, MM/BM), 256, GEMM_SMEM_BYTES>>>(hid, ww2, b2, nullptr, out, nullptr, nullptr, nullptr, HID, CC);
}

// round 11
// speedup vs baseline: 6.2835x; 1.1784x over previous
#include <cuda_runtime.h>
#include <cuda_fp16.h>
#include <cstdint>

#define BB   128
#define TT   256
#define CC   384
#define HH   6
#define DD   64
#define HID  1536
#define MM   (BB*TT)   // 32768
#define NQKV 1152

// GEMM tiling: CTA 128x128, 4 warps (2x2), warp tile 64x64, BK=32, 4-stage, 2 CTAs/SM
#define BM 128
#define BN 128
#define BK 32
#define ASTR 40
#define A_BUF_H (BM*ASTR)             // 5120 halves
#define B_BUF_H (BN*ASTR)             // 5120 halves
#define STG_H   (A_BUF_H + B_BUF_H)   // 10240 halves per stage
#define NSTG 4
#define GEMM_SMEM_BYTES (NSTG*STG_H*2)   // 81920 B

// attention smem strides (halves) — conflict-free
#define KSTR 72
#define VSTR 264
#define ATTN_SMEM_B ((TT*KSTR + DD*VSTR)*2)   // 70656

// ---------------- scratch ----------------
__device__ __half g_h[(size_t)MM*CC];
__device__ __half g_q[(size_t)BB*HH*TT*DD];
__device__ __half g_k[(size_t)BB*HH*TT*DD];
__device__ __half g_vt[(size_t)BB*HH*DD*TT];   // V transposed [b,h,d,t]
__device__ __half g_attn[(size_t)MM*CC];
__device__ __half g_hidden[(size_t)MM*HID];
__device__ __half g_w_qkv[(size_t)NQKV*CC];
__device__ __half g_w_proj[(size_t)CC*CC];
__device__ __half g_w1[(size_t)HID*CC];
__device__ __half g_w2[(size_t)CC*HID];

// ---------------- helpers ----------------
__device__ __forceinline__ void cp_async16(uint32_t s, const void* g) {
    asm volatile("cp.async.cg.shared.global [%0], [%1], 16;\n" :: "r"(s), "l"(g));
}
__device__ __forceinline__ void cp_commit() {
    asm volatile("cp.async.commit_group;\n");
}
template<int N> __device__ __forceinline__ void cp_wait() {
    asm volatile("cp.async.wait_group %0;\n" :: "n"(N));
}
__device__ __forceinline__ void mma16816(float* c, const uint32_t* a, const uint32_t* b) {
    asm volatile(
        "mma.sync.aligned.m16n8k16.row.col.f32.f16.f16.f32 "
        "{%0,%1,%2,%3}, {%4,%5,%6,%7}, {%8,%9}, {%0,%1,%2,%3};"
        : "+f"(c[0]), "+f"(c[1]), "+f"(c[2]), "+f"(c[3])
        : "r"(a[0]), "r"(a[1]), "r"(a[2]), "r"(a[3]), "r"(b[0]), "r"(b[1]));
}
__device__ __forceinline__ void ldsm_x4(uint32_t* r, uint32_t addr) {
    asm volatile("ldmatrix.sync.aligned.m8n8.x4.shared.b16 {%0,%1,%2,%3}, [%4];"
        : "=r"(r[0]), "=r"(r[1]), "=r"(r[2]), "=r"(r[3]) : "r"(addr));
}

// ---------------- fused weight pack ----------------
#define P_QKV  (CC*NQKV)
#define P_PRJ  (CC*CC)
#define P_W1   (CC*HID)
#define P_W2   (HID*CC)
#define P_TOT  (P_QKV + P_PRJ + P_W1 + P_W2)

__global__ void pack_all(const float* __restrict__ wq, const float* __restrict__ wk,
                         const float* __restrict__ wv, const float* __restrict__ wp,
                         const float* __restrict__ w1, const float* __restrict__ w2,
                         __half* __restrict__ oqkv, __half* __restrict__ oprj,
                         __half* __restrict__ ow1, __half* __restrict__ ow2)
{
    int idx = blockIdx.x * blockDim.x + threadIdx.x;
    if (idx >= P_TOT) return;
    if (idx < P_QKV) {
        int n = idx / CC, k = idx % CC;
        int src = n / CC, within = n % CC;
        int h = within >> 6, d = within & 63;
        const float* w = (src == 0) ? wq : (src == 1) ? wk : wv;
        oqkv[idx] = __float2half(w[((size_t)h*CC + k)*DD + d]);
    } else if (idx < P_QKV + P_PRJ) {
        int i = idx - P_QKV;
        int n = i / CC, k = i % CC;
        oprj[i] = __float2half(wp[(size_t)k*CC + n]);
    } else if (idx < P_QKV + P_PRJ + P_W1) {
        int i = idx - P_QKV - P_PRJ;
        int n = i / CC, k = i % CC;
        ow1[i] = __float2half(w1[(size_t)k*HID + n]);
    } else {
        int i = idx - P_QKV - P_PRJ - P_W1;
        int n = i / HID, k = i % HID;
        ow2[i] = __float2half(w2[(size_t)k*CC + n]);
    }
}

// ---------------- layernorm (fp16 output) ----------------
__global__ void ln_kernel(const float* __restrict__ x, const float* __restrict__ g,
                          const float* __restrict__ b, __half* __restrict__ out)
{
    int row = blockIdx.x;
    const float* xr = x + (size_t)row*CC;
    int t = threadIdx.x;
    float v0 = xr[t], v1 = xr[t+128], v2 = xr[t+256];
    float s  = v0+v1+v2;
    float ss = v0*v0 + v1*v1 + v2*v2;
    #pragma unroll
    for (int o = 16; o > 0; o >>= 1) {
        s  += __shfl_xor_sync(0xffffffffu, s,  o);
        ss += __shfl_xor_sync(0xffffffffu, ss, o);
    }
    __shared__ float sh_s[4], sh_ss[4];
    int w = t >> 5, lane = t & 31;
    if (lane == 0) { sh_s[w] = s; sh_ss[w] = ss; }
    __syncthreads();
    s  = sh_s[0]  + sh_s[1]  + sh_s[2]  + sh_s[3];
    ss = sh_ss[0] + sh_ss[1] + sh_ss[2] + sh_ss[3];
    float mean = s * (1.f/CC);
    float var  = ss * (1.f/CC) - mean*mean;
    float rstd = rsqrtf(var + 1e-5f);
    __half* orow = out + (size_t)row*CC;
    orow[t]     = __float2half((v0-mean)*rstd*g[t]     + b[t]);
    orow[t+128] = __float2half((v1-mean)*rstd*g[t+128] + b[t+128]);
    orow[t+256] = __float2half((v2-mean)*rstd*g[t+256] + b[t+256]);
}

// ---------------- fp16 tensor-core GEMM (4 warps, 64x64 each, 2 CTAs/SM) ----------------
// EPI: 0=QKV split; 1=proj(+bias+res)->f32; 2=fc1(relu)->fp16; 3=fc2(+bias,acc)->f32
template<int EPI>
__global__ __launch_bounds__(128, 2)
void gemm_f16(const __half* __restrict__ A, const __half* __restrict__ Bw,
              const float* __restrict__ bias, const float* __restrict__ res,
              float* __restrict__ outf, __half* __restrict__ outh,
              __half* __restrict__ out_k, __half* __restrict__ out_v,
              int K, int N)
{
    extern __shared__ __half smh[];
    uint32_t smem_u32 = (uint32_t)__cvta_generic_to_shared(smh);

    const int tid  = threadIdx.x;
    const int bm   = blockIdx.y * BM;
    const int bn   = blockIdx.x * BN;
    const int warp = tid >> 5, lane = tid & 31;
    const int wm   = (warp >> 1) * 64;    // 2 warp rows
    const int wn   = (warp & 1)  * 64;    // 2 warp cols
    const int gid  = lane >> 2, tig = lane & 3;

    // ldmatrix lane-address components
    const int aRow = wm + (lane & 15);              // + mt*16
    const int aK   = (lane >> 4) << 3;              // 0 or 8
    const int bRow = wn + (lane & 7) + ((lane & 16) ? 8 : 0);   // + p*16
    const int bK   = (lane & 8);                    // 0 or 8

    float acc[4][8][4];
    #pragma unroll
    for (int mt = 0; mt < 4; mt++)
        #pragma unroll
        for (int nt = 0; nt < 8; nt++)
            #pragma unroll
            for (int r = 0; r < 4; r++) acc[mt][nt][r] = 0.f;

    // global loads with 128 threads: A 128x32 = 512 chunks (4/thread); B same
    auto load_tile = [&](int k0, int buf) {
        #pragma unroll
        for (int i = 0; i < 4; i++) {
            int c = tid + i*128;
            int row = c >> 2, co = (c & 3) * 8;
            uint32_t s = smem_u32 + (uint32_t)(buf*STG_H + row*ASTR + co)*2u;
            cp_async16(s, A + (size_t)(bm + row)*K + k0 + co);
        }
        #pragma unroll
        for (int i = 0; i < 4; i++) {
            int c = tid + i*128;
            int row = c >> 2, co = (c & 3) * 8;
            uint32_t s = smem_u32 + (uint32_t)(buf*STG_H + A_BUF_H + row*ASTR + co)*2u;
            cp_async16(s, Bw + (size_t)(bn + row)*K + k0 + co);
        }
        cp_commit();
    };

    const int ntiles = K / BK;
    load_tile(0, 0);
    if (ntiles > 1) load_tile(BK, 1);
    if (ntiles > 2) load_tile(2*BK, 2);

    for (int kt = 0; kt < ntiles; kt++) {
        if (kt + 1 < ntiles) cp_wait<2>(); else cp_wait<0>();
        __syncthreads();
        int cur = kt % NSTG;
        if (kt + 3 < ntiles) load_tile((kt+3)*BK, (kt+3) % NSTG);

        const uint32_t aBase = smem_u32 + (uint32_t)(cur*STG_H + aRow*ASTR + aK)*2u;
        const uint32_t bBase = smem_u32 + (uint32_t)(cur*STG_H + A_BUF_H + bRow*ASTR + bK)*2u;

        #pragma unroll
        for (int ks = 0; ks < 2; ks++) {
            const int k0 = ks * 16;
            uint32_t a[4][4];
            #pragma unroll
            for (int mt = 0; mt < 4; mt++)
                ldsm_x4(a[mt], aBase + (uint32_t)(mt*16*ASTR + k0)*2u);
            uint32_t b[8][2];
            #pragma unroll
            for (int p = 0; p < 4; p++) {
                uint32_t r[4];
                ldsm_x4(r, bBase + (uint32_t)(p*16*ASTR + k0)*2u);
                b[2*p][0]   = r[0];
                b[2*p][1]   = r[1];
                b[2*p+1][0] = r[2];
                b[2*p+1][1] = r[3];
            }
            #pragma unroll
            for (int mt = 0; mt < 4; mt++)
                #pragma unroll
                for (int nt = 0; nt < 8; nt++)
                    mma16816(acc[mt][nt], a[mt], b[nt]);
        }
    }

    // epilogue — paired stores
    #pragma unroll
    for (int mt = 0; mt < 4; mt++) {
        #pragma unroll
        for (int nt = 0; nt < 8; nt++) {
            int row0 = bm + wm + mt*16 + gid;
            int col  = bn + wn + nt*8 + tig*2;
            #pragma unroll
            for (int h2 = 0; h2 < 2; h2++) {
                int row = row0 + h2*8;
                float v0 = acc[mt][nt][h2*2];
                float v1 = acc[mt][nt][h2*2+1];
                if (EPI == 0) {
                    int src = col / CC, within = col % CC;
                    int h = within >> 6, d = within & 63;
                    int bidx = row / TT, t = row % TT;
                    if (src == 0)
                        *(__half2*)&outh[(((size_t)bidx*HH + h)*TT + t)*DD + d] = __floats2half2_rn(v0, v1);
                    else if (src == 1)
                        *(__half2*)&out_k[(((size_t)bidx*HH + h)*TT + t)*DD + d] = __floats2half2_rn(v0, v1);
                    else {
                        out_v[(((size_t)bidx*HH + h)*DD + d)*TT + t]     = __float2half(v0);
                        out_v[(((size_t)bidx*HH + h)*DD + d + 1)*TT + t] = __float2half(v1);
                    }
                } else if (EPI == 1) {
                    const float2 rv = *(const float2*)&res[(size_t)row*N + col];
                    float2 o;
                    o.x = v0 + bias[col]   + rv.x;
                    o.y = v1 + bias[col+1] + rv.y;
                    *(float2*)&outf[(size_t)row*N + col] = o;
                } else if (EPI == 2) {
                    *(__half2*)&outh[(size_t)row*N + col] =
                        __floats2half2_rn(fmaxf(v0 + bias[col], 0.f), fmaxf(v1 + bias[col+1], 0.f));
                } else {
                    float2 o = *(const float2*)&outf[(size_t)row*N + col];
                    o.x += v0 + bias[col];
                    o.y += v1 + bias[col+1];
                    *(float2*)&outf[(size_t)row*N + col] = o;
                }
            }
        }
    }
}

// ---------------- tensor-core flash attention ----------------
__global__ __launch_bounds__(128, 2)
void attn_mma(const __half* __restrict__ q, const __half* __restrict__ k,
              const __half* __restrict__ vt, __half* __restrict__ out)
{
    extern __shared__ __half sm[];
    __half* Ks = sm;
    __half* Vs = sm + TT*KSTR;
    uint32_t smemK = (uint32_t)__cvta_generic_to_shared(Ks);
    uint32_t smemV = (uint32_t)__cvta_generic_to_shared(Vs);

    const int half_ = blockIdx.x, hh = blockIdx.y, b = blockIdx.z;
    const int bh = b*HH + hh;
    const int tid = threadIdx.x, warp = tid >> 5, lane = tid & 31;
    const int gid = lane >> 2, tig = lane & 3;
    const int ntok = (half_ + 1) * 128;

    const __half* kg = k + (size_t)bh*TT*DD;
    for (int c = tid; c < ntok*8; c += 128) {
        int row = c >> 3, co = (c & 7)*8;
        cp_async16(smemK + (uint32_t)(row*KSTR + co)*2u, kg + row*DD + co);
    }
    const __half* vg = vt + (size_t)bh*DD*TT;
    const int vch = ntok >> 3;
    for (int c = tid; c < DD*vch; c += 128) {
        int d = c / vch, co = (c % vch)*8;
        cp_async16(smemV + (uint32_t)(d*VSTR + co)*2u, vg + d*TT + co);
    }
    cp_commit();

    const int rowbase = half_*128 + warp*32;
    const __half* qg = q + ((size_t)bh*TT + rowbase)*DD;
    uint32_t qf[2][4][4];
    #pragma unroll
    for (int mt = 0; mt < 2; mt++)
        #pragma unroll
        for (int f = 0; f < 4; f++) {
            const __half* p0 = qg + (mt*16 + gid)*DD + f*16 + 2*tig;
            qf[mt][f][0] = *(const uint32_t*)(p0);
            qf[mt][f][1] = *(const uint32_t*)(p0 + 8*DD);
            qf[mt][f][2] = *(const uint32_t*)(p0 + 8);
            qf[mt][f][3] = *(const uint32_t*)(p0 + 8*DD + 8);
        }

    float o[2][8][4];
    #pragma unroll
    for (int mt = 0; mt < 2; mt++)
        #pragma unroll
        for (int nt = 0; nt < 8; nt++)
            #pragma unroll
            for (int r = 0; r < 4; r++) o[mt][nt][r] = 0.f;
    float mrow[2][2] = {{-1e30f,-1e30f},{-1e30f,-1e30f}};
    float lrow[2][2] = {{0.f,0.f},{0.f,0.f}};
    const float scale = rsqrtf((float)CC);

    cp_wait<0>();
    __syncthreads();

    const int ntiles = (rowbase + 32 + 63) >> 6;
    for (int t = 0; t < ntiles; t++) {
        float s[2][8][4];
        #pragma unroll
        for (int mt = 0; mt < 2; mt++)
            #pragma unroll
            for (int nt = 0; nt < 8; nt++)
                #pragma unroll
                for (int r = 0; r < 4; r++) s[mt][nt][r] = 0.f;

        #pragma unroll
        for (int f = 0; f < 4; f++) {
            uint32_t bf[8][2];
            #pragma unroll
            for (int nt = 0; nt < 8; nt++) {
                const __half* bp = Ks + (t*64 + nt*8 + gid)*KSTR + f*16 + 2*tig;
                bf[nt][0] = *(const uint32_t*)(bp);
                bf[nt][1] = *(const uint32_t*)(bp + 8);
            }
            #pragma unroll
            for (int mt = 0; mt < 2; mt++)
                #pragma unroll
                for (int nt = 0; nt < 8; nt++)
                    mma16816(s[mt][nt], qf[mt][f], bf[nt]);
        }

        uint32_t pf[2][4][4];
        #pragma unroll
        for (int mt = 0; mt < 2; mt++) {
            const int rA = rowbase + mt*16 + gid;
            const int rB = rA + 8;
            #pragma unroll
            for (int nt = 0; nt < 8; nt++) {
                int c0 = t*64 + nt*8 + 2*tig;
                if (c0     > rA) s[mt][nt][0] = -1e30f;
                if (c0 + 1 > rA) s[mt][nt][1] = -1e30f;
                if (c0     > rB) s[mt][nt][2] = -1e30f;
                if (c0 + 1 > rB) s[mt][nt][3] = -1e30f;
            }
            float mxA = -1e30f, mxB = -1e30f;
            #pragma unroll
            for (int nt = 0; nt < 8; nt++) {
                mxA = fmaxf(mxA, fmaxf(s[mt][nt][0], s[mt][nt][1]));
                mxB = fmaxf(mxB, fmaxf(s[mt][nt][2], s[mt][nt][3]));
            }
            mxA = fmaxf(mxA, __shfl_xor_sync(0xffffffffu, mxA, 1));
            mxA = fmaxf(mxA, __shfl_xor_sync(0xffffffffu, mxA, 2));
            mxB = fmaxf(mxB, __shfl_xor_sync(0xffffffffu, mxB, 1));
            mxB = fmaxf(mxB, __shfl_xor_sync(0xffffffffu, mxB, 2));

            float mnA = fmaxf(mrow[mt][0], mxA);
            float mnB = fmaxf(mrow[mt][1], mxB);
            float cA  = __expf(scale*(mrow[mt][0] - mnA));
            float cB  = __expf(scale*(mrow[mt][1] - mnB));
            mrow[mt][0] = mnA; mrow[mt][1] = mnB;

            float sA = 0.f, sB = 0.f;
            #pragma unroll
            for (int nt = 0; nt < 8; nt++) {
                s[mt][nt][0] = __expf(scale*(s[mt][nt][0] - mnA));
                s[mt][nt][1] = __expf(scale*(s[mt][nt][1] - mnA));
                s[mt][nt][2] = __expf(scale*(s[mt][nt][2] - mnB));
                s[mt][nt][3] = __expf(scale*(s[mt][nt][3] - mnB));
                sA += s[mt][nt][0] + s[mt][nt][1];
                sB += s[mt][nt][2] + s[mt][nt][3];
            }
            sA += __shfl_xor_sync(0xffffffffu, sA, 1);
            sA += __shfl_xor_sync(0xffffffffu, sA, 2);
            sB += __shfl_xor_sync(0xffffffffu, sB, 1);
            sB += __shfl_xor_sync(0xffffffffu, sB, 2);
            lrow[mt][0] = lrow[mt][0]*cA + sA;
            lrow[mt][1] = lrow[mt][1]*cB + sB;

            #pragma unroll
            for (int nt = 0; nt < 8; nt++) {
                o[mt][nt][0] *= cA; o[mt][nt][1] *= cA;
                o[mt][nt][2] *= cB; o[mt][nt][3] *= cB;
            }
            #pragma unroll
            for (int f = 0; f < 4; f++) {
                __half2 h0 = __floats2half2_rn(s[mt][2*f][0],   s[mt][2*f][1]);
                __half2 h1 = __floats2half2_rn(s[mt][2*f][2],   s[mt][2*f][3]);
                __half2 h2 = __floats2half2_rn(s[mt][2*f+1][0], s[mt][2*f+1][1]);
                __half2 h3 = __floats2half2_rn(s[mt][2*f+1][2], s[mt][2*f+1][3]);
                pf[mt][f][0] = *(uint32_t*)&h0;
                pf[mt][f][1] = *(uint32_t*)&h1;
                pf[mt][f][2] = *(uint32_t*)&h2;
                pf[mt][f][3] = *(uint32_t*)&h3;
            }
        }

        #pragma unroll
        for (int f = 0; f < 4; f++) {
            uint32_t vb[8][2];
            #pragma unroll
            for (int nt = 0; nt < 8; nt++) {
                const __half* vp = Vs + (nt*8 + gid)*VSTR + t*64 + f*16 + 2*tig;
                vb[nt][0] = *(const uint32_t*)(vp);
                vb[nt][1] = *(const uint32_t*)(vp + 8);
            }
            #pragma unroll
            for (int mt = 0; mt < 2; mt++)
                #pragma unroll
                for (int nt = 0; nt < 8; nt++)
                    mma16816(o[mt][nt], pf[mt][f], vb[nt]);
        }
    }

    #pragma unroll
    for (int mt = 0; mt < 2; mt++) {
        float invA = 1.f / lrow[mt][0];
        float invB = 1.f / lrow[mt][1];
        int rA = rowbase + mt*16 + gid;
        int rB = rA + 8;
        __half* oA = out + ((size_t)b*TT + rA)*CC + hh*DD;
        __half* oB = out + ((size_t)b*TT + rB)*CC + hh*DD;
        #pragma unroll
        for (int nt = 0; nt < 8; nt++) {
            __half2 hA = __floats2half2_rn(o[mt][nt][0]*invA, o[mt][nt][1]*invA);
            __half2 hB = __floats2half2_rn(o[mt][nt][2]*invB, o[mt][nt][3]*invB);
            *(__half2*)(oA + nt*8 + 2*tig) = hA;
            *(__half2*)(oB + nt*8 + 2*tig) = hB;
        }
    }
}

// ---------------- launch ----------------
extern "C" void kernel_launch(void* const* d_in, const int* in_sizes, int n_in,
                              void* d_out, int out_size)
{
    const float* x      = (const float*)d_in[0];
    const float* wq     = (const float*)d_in[1];
    const float* wk     = (const float*)d_in[2];
    const float* wv     = (const float*)d_in[3];
    const float* w_proj = (const float*)d_in[4];
    const float* b_proj = (const float*)d_in[5];
    const float* w1     = (const float*)d_in[6];
    const float* b1     = (const float*)d_in[7];
    const float* w2     = (const float*)d_in[8];
    const float* b2     = (const float*)d_in[9];
    const float* ln1_g  = (const float*)d_in[10];
    const float* ln1_b  = (const float*)d_in[11];
    const float* ln2_g  = (const float*)d_in[12];
    const float* ln2_b  = (const float*)d_in[13];
    float* out = (float*)d_out;

    void* p;
    cudaGetSymbolAddress(&p, g_h);      __half* h     = (__half*)p;
    cudaGetSymbolAddress(&p, g_q);      __half* q     = (__half*)p;
    cudaGetSymbolAddress(&p, g_k);      __half* k     = (__half*)p;
    cudaGetSymbolAddress(&p, g_vt);     __half* vt    = (__half*)p;
    cudaGetSymbolAddress(&p, g_attn);   __half* attn  = (__half*)p;
    cudaGetSymbolAddress(&p, g_hidden); __half* hid   = (__half*)p;
    cudaGetSymbolAddress(&p, g_w_qkv);  __half* wqkv  = (__half*)p;
    cudaGetSymbolAddress(&p, g_w_proj); __half* wprj  = (__half*)p;
    cudaGetSymbolAddress(&p, g_w1);     __half* ww1   = (__half*)p;
    cudaGetSymbolAddress(&p, g_w2);     __half* ww2   = (__half*)p;

    cudaFuncSetAttribute(attn_mma, cudaFuncAttributeMaxDynamicSharedMemorySize, ATTN_SMEM_B);
    cudaFuncSetAttribute(gemm_f16<0>, cudaFuncAttributeMaxDynamicSharedMemorySize, GEMM_SMEM_BYTES);
    cudaFuncSetAttribute(gemm_f16<1>, cudaFuncAttributeMaxDynamicSharedMemorySize, GEMM_SMEM_BYTES);
    cudaFuncSetAttribute(gemm_f16<2>, cudaFuncAttributeMaxDynamicSharedMemorySize, GEMM_SMEM_BYTES);
    cudaFuncSetAttribute(gemm_f16<3>, cudaFuncAttributeMaxDynamicSharedMemorySize, GEMM_SMEM_BYTES);

    // 0. weight pack
    pack_all<<<(P_TOT + 255)/256, 256>>>(wq, wk, wv, w_proj, w1, w2, wqkv, wprj, ww1, ww2);

    // 1. LN1 -> h
    ln_kernel<<<MM, 128>>>(x, ln1_g, ln1_b, h);

    // 2. fused QKV -> q, k (fp16 [b,h,t,d]), v transposed (fp16 [b,h,d,t])
    gemm_f16<0><<<dim3(NQKV/BN, MM/BM), 128, GEMM_SMEM_BYTES>>>(h, wqkv, nullptr, nullptr, nullptr, q, k, vt, CC, NQKV);

    // 3. tensor-core flash attention -> attn (fp16)
    attn_mma<<<dim3(2, HH, BB), 128, ATTN_SMEM_B>>>(q, k, vt, attn);

    // 4. proj + bias + residual(x) -> d_out
    gemm_f16<1><<<dim3(CC/BN, MM/BM), 128, GEMM_SMEM_BYTES>>>(attn, wprj, b_proj, x, out, nullptr, nullptr, nullptr, CC, CC);

    // 5. LN2 -> h
    ln_kernel<<<MM, 128>>>(out, ln2_g, ln2_b, h);

    // 6. fc1 + bias + relu -> hidden (fp16)
    gemm_f16<2><<<dim3(HID/BN, MM/BM), 128, GEMM_SMEM_BYTES>>>(h, ww1, b1, nullptr, nullptr, hid, nullptr, nullptr, CC, HID);

    // 7. fc2 + bias, accumulate into d_out
    gemm_f16<3><<<dim3(CC/BN, MM/BM), 128, GEMM_SMEM_BYTES>>>(hid, ww2, b2, nullptr, out, nullptr, nullptr, nullptr, HID, CC);
}